// round 1
// baseline (speedup 1.0000x reference)
#include <cuda_runtime.h>
#include <math.h>

// ---------------- problem constants ----------------
#define HIDDEN   768
#define MLPH     3072
#define HEADS    12
#define HEAD_DIM 64
#define BATCH    16
#define SEQ      1024
#define MTOK     (BATCH * SEQ)          // 16384 tokens

// ---------------- scratch (device globals; no allocation) ----------------
__device__ float g_xn  [(size_t)MTOK * HIDDEN];   // LN output (reused for LN2 output)
__device__ float g_q   [(size_t)MTOK * HIDDEN];
__device__ float g_k   [(size_t)MTOK * HIDDEN];
__device__ float g_v   [(size_t)MTOK * HIDDEN];
__device__ float g_attn[(size_t)MTOK * HIDDEN];
__device__ float g_x1  [(size_t)MTOK * HIDDEN];   // after attention residual
__device__ float g_h   [(size_t)MTOK * MLPH];     // MLP hidden
__device__ float g_sc  [(size_t)BATCH * HEADS * SEQ * SEQ];  // attention scores (805 MB)

// ---------------- reduction helpers ----------------
__device__ __forceinline__ float warp_sum(float v) {
    #pragma unroll
    for (int o = 16; o; o >>= 1) v += __shfl_xor_sync(0xffffffffu, v, o);
    return v;
}
__device__ __forceinline__ float warp_max(float v) {
    #pragma unroll
    for (int o = 16; o; o >>= 1) v = fmaxf(v, __shfl_xor_sync(0xffffffffu, v, o));
    return v;
}

// ---------------- LayerNorm: one block per row of 768 ----------------
__global__ __launch_bounds__(256)
void ln_k(const float* __restrict__ x, const float* __restrict__ g,
          const float* __restrict__ b, float* __restrict__ out)
{
    long row = blockIdx.x;
    const float* xr = x + row * (long)HIDDEN;
    int tid = threadIdx.x;

    float v0 = xr[tid], v1 = xr[tid + 256], v2 = xr[tid + 512];
    float s  = v0 + v1 + v2;
    float s2 = v0 * v0 + v1 * v1 + v2 * v2;

    __shared__ float sh[18];
    s  = warp_sum(s);
    s2 = warp_sum(s2);
    int w = tid >> 5, l = tid & 31;
    if (!l) { sh[w] = s; sh[w + 8] = s2; }
    __syncthreads();
    if (tid == 0) {
        float ts = 0.f, ts2 = 0.f;
        #pragma unroll
        for (int i = 0; i < 8; i++) { ts += sh[i]; ts2 += sh[i + 8]; }
        float mu  = ts  * (1.0f / HIDDEN);
        float var = ts2 * (1.0f / HIDDEN) - mu * mu;
        sh[16] = mu;
        sh[17] = rsqrtf(var + 1e-5f);
    }
    __syncthreads();
    float mu = sh[16], inv = sh[17];

    float* o = out + row * (long)HIDDEN;
    o[tid]       = (v0 - mu) * inv * g[tid]       + b[tid];
    o[tid + 256] = (v1 - mu) * inv * g[tid + 256] + b[tid + 256];
    o[tid + 512] = (v2 - mu) * inv * g[tid + 512] + b[tid + 512];
}

// ---------------- softmax over rows of 1024 (scale folded in) ----------------
__global__ __launch_bounds__(256)
void softmax_k(float* __restrict__ sc)
{
    long row = blockIdx.x;
    float* p = sc + row * (long)SEQ;
    int tid = threadIdx.x;
    const float scale = 0.125f;  // HEAD_DIM^-0.5

    float v[4];
    #pragma unroll
    for (int i = 0; i < 4; i++) v[i] = p[tid + i * 256];

    float m = fmaxf(fmaxf(v[0], v[1]), fmaxf(v[2], v[3]));
    __shared__ float sh[10];
    m = warp_max(m);
    int w = tid >> 5, l = tid & 31;
    if (!l) sh[w] = m;
    __syncthreads();
    if (tid == 0) {
        float t = sh[0];
        #pragma unroll
        for (int i = 1; i < 8; i++) t = fmaxf(t, sh[i]);
        sh[8] = t;
    }
    __syncthreads();
    m = sh[8];

    float s = 0.f;
    #pragma unroll
    for (int i = 0; i < 4; i++) { v[i] = __expf((v[i] - m) * scale); s += v[i]; }
    s = warp_sum(s);
    if (!l) sh[w] = s;
    __syncthreads();
    if (tid == 0) {
        float t = 0.f;
        #pragma unroll
        for (int i = 0; i < 8; i++) t += sh[i];
        sh[9] = 1.0f / t;
    }
    __syncthreads();
    float r = sh[9];
    #pragma unroll
    for (int i = 0; i < 4; i++) p[tid + i * 256] = v[i] * r;
}

// ---------------- generic tiled FP32 GEMM ----------------
// C[M,N] = A[M,K] @ op(B), op(B)=B^T if TRANSB (B is [N,K] row-major, leading dim ldb),
// else B is [K,N] row-major (leading dim ldb).
// Batched via grid.z: z -> (ob = z / zInner, ib = z % zInner), each matrix offset by
// ob*so + ib*si. EPI: 0 = store, 1 = +bias[col] + resid[row,col], 2 = +bias[col] then exact GELU.
#define BM 128
#define BN 64
#define BK 16
#define TM 8
#define TN 4

template<bool TRANSB, int EPI>
__global__ __launch_bounds__(256)
void gemm_k(const float* __restrict__ A, int lda, long soA, long siA,
            const float* __restrict__ Bp, int ldb, long soB, long siB,
            float* __restrict__ C, int ldc, long soC, long siC,
            int M, int N, int K, int zInner,
            const float* __restrict__ bias,
            const float* __restrict__ resid, int ldr)
{
    int z  = blockIdx.z;
    int ob = z / zInner;
    int ib = z - ob * zInner;
    A  += ob * soA + ib * siA;
    Bp += ob * soB + ib * siB;
    C  += ob * soC + ib * siC;

    __shared__ float As[BK][BM];
    __shared__ float Bs[BK][BN];

    int tid = threadIdx.x;
    int tx = tid & 15, ty = tid >> 4;
    int m0 = blockIdx.y * BM, n0 = blockIdx.x * BN;

    float acc[TM][TN] = {};

    for (int k0 = 0; k0 < K; k0 += BK) {
        // load A tile: 128x16 = 512 float4s, 2 per thread
        #pragma unroll
        for (int r = 0; r < 2; r++) {
            int f   = tid + r * 256;
            int row = f >> 2;
            int c4  = (f & 3) * 4;
            float4 va = *reinterpret_cast<const float4*>(&A[(long)(m0 + row) * lda + k0 + c4]);
            As[c4 + 0][row] = va.x; As[c4 + 1][row] = va.y;
            As[c4 + 2][row] = va.z; As[c4 + 3][row] = va.w;
        }
        // load B tile
        if (TRANSB) {
            int n  = tid >> 2;
            int c4 = (tid & 3) * 4;
            float4 vb = *reinterpret_cast<const float4*>(&Bp[(long)(n0 + n) * ldb + k0 + c4]);
            Bs[c4 + 0][n] = vb.x; Bs[c4 + 1][n] = vb.y;
            Bs[c4 + 2][n] = vb.z; Bs[c4 + 3][n] = vb.w;
        } else {
            int kk = tid >> 4;
            int c4 = (tid & 15) * 4;
            float4 vb = *reinterpret_cast<const float4*>(&Bp[(long)(k0 + kk) * ldb + n0 + c4]);
            *reinterpret_cast<float4*>(&Bs[kk][c4]) = vb;
        }
        __syncthreads();

        #pragma unroll
        for (int kk = 0; kk < BK; kk++) {
            float4 a0 = *reinterpret_cast<const float4*>(&As[kk][ty * TM]);
            float4 a1 = *reinterpret_cast<const float4*>(&As[kk][ty * TM + 4]);
            float4 bv = *reinterpret_cast<const float4*>(&Bs[kk][tx * TN]);
            float ar[TM] = {a0.x, a0.y, a0.z, a0.w, a1.x, a1.y, a1.z, a1.w};
            float br[TN] = {bv.x, bv.y, bv.z, bv.w};
            #pragma unroll
            for (int i = 0; i < TM; i++)
                #pragma unroll
                for (int j = 0; j < TN; j++)
                    acc[i][j] = fmaf(ar[i], br[j], acc[i][j]);
        }
        __syncthreads();
    }

    // epilogue (TN=4 contiguous columns -> float4 store)
    int colb = n0 + tx * TN;
    #pragma unroll
    for (int i = 0; i < TM; i++) {
        int row = m0 + ty * TM + i;
        float vo[TN];
        #pragma unroll
        for (int j = 0; j < TN; j++) {
            float v = acc[i][j];
            if (EPI == 1) {
                v += bias[colb + j] + resid[(long)row * ldr + colb + j];
            } else if (EPI == 2) {
                v += bias[colb + j];
                v = 0.5f * v * (1.0f + erff(v * 0.70710678118654752f));
            }
            vo[j] = v;
        }
        *reinterpret_cast<float4*>(&C[(long)row * ldc + colb]) =
            make_float4(vo[0], vo[1], vo[2], vo[3]);
    }
}

// ---------------- launcher ----------------
extern "C" void kernel_launch(void* const* d_in, const int* in_sizes, int n_in,
                              void* d_out, int out_size)
{
    const float* x    = (const float*)d_in[0];
    const float* ln1g = (const float*)d_in[1];
    const float* ln1b = (const float*)d_in[2];
    const float* wq   = (const float*)d_in[3];
    const float* wk   = (const float*)d_in[4];
    const float* wv   = (const float*)d_in[5];
    const float* wo   = (const float*)d_in[6];
    const float* bo   = (const float*)d_in[7];
    const float* ln2g = (const float*)d_in[8];
    const float* ln2b = (const float*)d_in[9];
    const float* w1   = (const float*)d_in[10];
    const float* b1   = (const float*)d_in[11];
    const float* w2   = (const float*)d_in[12];
    const float* b2   = (const float*)d_in[13];
    float* out = (float*)d_out;

    float *xn, *q, *k, *v, *attn, *x1, *hm, *sc;
    cudaGetSymbolAddress((void**)&xn,   g_xn);
    cudaGetSymbolAddress((void**)&q,    g_q);
    cudaGetSymbolAddress((void**)&k,    g_k);
    cudaGetSymbolAddress((void**)&v,    g_v);
    cudaGetSymbolAddress((void**)&attn, g_attn);
    cudaGetSymbolAddress((void**)&x1,   g_x1);
    cudaGetSymbolAddress((void**)&hm,   g_h);
    cudaGetSymbolAddress((void**)&sc,   g_sc);

    const long sQA = (long)SEQ * HIDDEN;     // per-batch stride in q/k/v/attn
    const long sHA = HEAD_DIM;               // per-head stride in q/k/v/attn
    const long sQS = (long)HEADS * SEQ * SEQ;// per-batch stride in scores
    const long sHS = (long)SEQ * SEQ;        // per-head stride in scores

    // 1. LN1
    ln_k<<<MTOK, 256>>>(x, ln1g, ln1b, xn);

    // 2. Q, K, V = xn @ W^T   (M=16384, N=768, K=768)
    dim3 gQKV(HIDDEN / BN, MTOK / BM, 1);
    gemm_k<true, 0><<<gQKV, 256>>>(xn, HIDDEN, 0, 0, wq, HIDDEN, 0, 0,
                                   q, HIDDEN, 0, 0, MTOK, HIDDEN, HIDDEN, 1,
                                   nullptr, nullptr, 0);
    gemm_k<true, 0><<<gQKV, 256>>>(xn, HIDDEN, 0, 0, wk, HIDDEN, 0, 0,
                                   k, HIDDEN, 0, 0, MTOK, HIDDEN, HIDDEN, 1,
                                   nullptr, nullptr, 0);
    gemm_k<true, 0><<<gQKV, 256>>>(xn, HIDDEN, 0, 0, wv, HIDDEN, 0, 0,
                                   v, HIDDEN, 0, 0, MTOK, HIDDEN, HIDDEN, 1,
                                   nullptr, nullptr, 0);

    // 3. scores[b,h] = Q_bh @ K_bh^T   (batched over 192 heads; M=N=1024, K=64)
    dim3 gS(SEQ / BN, SEQ / BM, BATCH * HEADS);
    gemm_k<true, 0><<<gS, 256>>>(q, HIDDEN, sQA, sHA, k, HIDDEN, sQA, sHA,
                                 sc, SEQ, sQS, sHS, SEQ, SEQ, HEAD_DIM, HEADS,
                                 nullptr, nullptr, 0);

    // 4. softmax rows (scale folded in)
    softmax_k<<<BATCH * HEADS * SEQ, 256>>>(sc);

    // 5. attn[b,h] = P_bh @ V_bh      (M=1024, N=64, K=1024)
    dim3 gPV(HEAD_DIM / BN, SEQ / BM, BATCH * HEADS);
    gemm_k<false, 0><<<gPV, 256>>>(sc, SEQ, sQS, sHS, v, HIDDEN, sQA, sHA,
                                   attn, HIDDEN, sQA, sHA, SEQ, HEAD_DIM, SEQ, HEADS,
                                   nullptr, nullptr, 0);

    // 6. x1 = attn @ wo^T + bo + x
    gemm_k<true, 1><<<gQKV, 256>>>(attn, HIDDEN, 0, 0, wo, HIDDEN, 0, 0,
                                   x1, HIDDEN, 0, 0, MTOK, HIDDEN, HIDDEN, 1,
                                   bo, x, HIDDEN);

    // 7. LN2 (reuse xn)
    ln_k<<<MTOK, 256>>>(x1, ln2g, ln2b, xn);

    // 8. h = gelu(xn @ w1 + b1)  (M=16384, N=3072, K=768; w1 is [K,N])
    dim3 gW1(MLPH / BN, MTOK / BM, 1);
    gemm_k<false, 2><<<gW1, 256>>>(xn, HIDDEN, 0, 0, w1, MLPH, 0, 0,
                                   hm, MLPH, 0, 0, MTOK, MLPH, HIDDEN, 1,
                                   b1, nullptr, 0);

    // 9. out = h @ w2 + b2 + x1  (M=16384, N=768, K=3072; w2 is [K,N])
    gemm_k<false, 1><<<gQKV, 256>>>(hm, MLPH, 0, 0, w2, HIDDEN, 0, 0,
                                    out, HIDDEN, 0, 0, MTOK, HIDDEN, MLPH, 1,
                                    b2, x1, HIDDEN);
}

// round 3
// speedup vs baseline: 2.3951x; 2.3951x over previous
#include <cuda_runtime.h>
#include <math.h>
#include <stdint.h>

// ---------------- problem constants ----------------
#define HIDDEN   768
#define MLPH     3072
#define HEADS    12
#define HEAD_DIM 64
#define BATCH    16
#define SEQ      1024
#define MTOK     (BATCH * SEQ)

// ---------------- scratch (device globals; no allocation) ----------------
__device__ float g_xn  [(size_t)MTOK * HIDDEN];
__device__ float g_q   [(size_t)MTOK * HIDDEN];
__device__ float g_k   [(size_t)MTOK * HIDDEN];
__device__ float g_v   [(size_t)MTOK * HIDDEN];
__device__ float g_vt  [(size_t)BATCH * HEADS * HEAD_DIM * SEQ];
__device__ float g_attn[(size_t)MTOK * HIDDEN];
__device__ float g_x1  [(size_t)MTOK * HIDDEN];
__device__ float g_h   [(size_t)MTOK * MLPH];
__device__ float g_sc  [(size_t)BATCH * HEADS * SEQ * SEQ];
__device__ float g_w1t [(size_t)MLPH * HIDDEN];
__device__ float g_w2t [(size_t)HIDDEN * MLPH];

// ---------------- helpers ----------------
__device__ __forceinline__ uint32_t f2tf(float f) {
    uint32_t r; asm("cvt.rna.tf32.f32 %0, %1;" : "=r"(r) : "f"(f)); return r;
}
__device__ __forceinline__ void mma_tf32(float* d, const uint32_t* a, const uint32_t* b) {
    asm volatile("mma.sync.aligned.m16n8k8.row.col.f32.tf32.tf32.f32 "
                 "{%0,%1,%2,%3}, {%4,%5,%6,%7}, {%8,%9}, {%0,%1,%2,%3};"
                 : "+f"(d[0]), "+f"(d[1]), "+f"(d[2]), "+f"(d[3])
                 : "r"(a[0]), "r"(a[1]), "r"(a[2]), "r"(a[3]), "r"(b[0]), "r"(b[1]));
}
__device__ __forceinline__ float warp_sum(float v) {
    #pragma unroll
    for (int o = 16; o; o >>= 1) v += __shfl_xor_sync(0xffffffffu, v, o);
    return v;
}
__device__ __forceinline__ float warp_max(float v) {
    #pragma unroll
    for (int o = 16; o; o >>= 1) v = fmaxf(v, __shfl_xor_sync(0xffffffffu, v, o));
    return v;
}

// ---------------- LayerNorm ----------------
__global__ __launch_bounds__(256)
void ln_k(const float* __restrict__ x, const float* __restrict__ g,
          const float* __restrict__ b, float* __restrict__ out)
{
    long row = blockIdx.x;
    const float* xr = x + row * (long)HIDDEN;
    int tid = threadIdx.x;
    float v0 = xr[tid], v1 = xr[tid + 256], v2 = xr[tid + 512];
    float s  = v0 + v1 + v2;
    float s2 = v0 * v0 + v1 * v1 + v2 * v2;
    __shared__ float sh[18];
    s = warp_sum(s); s2 = warp_sum(s2);
    int w = tid >> 5, l = tid & 31;
    if (!l) { sh[w] = s; sh[w + 8] = s2; }
    __syncthreads();
    if (tid == 0) {
        float ts = 0.f, ts2 = 0.f;
        #pragma unroll
        for (int i = 0; i < 8; i++) { ts += sh[i]; ts2 += sh[i + 8]; }
        float mu  = ts * (1.0f / HIDDEN);
        float var = ts2 * (1.0f / HIDDEN) - mu * mu;
        sh[16] = mu; sh[17] = rsqrtf(var + 1e-5f);
    }
    __syncthreads();
    float mu = sh[16], inv = sh[17];
    float* o = out + row * (long)HIDDEN;
    o[tid]       = (v0 - mu) * inv * g[tid]       + b[tid];
    o[tid + 256] = (v1 - mu) * inv * g[tid + 256] + b[tid + 256];
    o[tid + 512] = (v2 - mu) * inv * g[tid + 512] + b[tid + 512];
}

// ---------------- softmax (scale folded in) ----------------
__global__ __launch_bounds__(256)
void softmax_k(float* __restrict__ sc)
{
    long row = blockIdx.x;
    float* p = sc + row * (long)SEQ;
    int tid = threadIdx.x;
    const float scale = 0.125f;
    float v[4];
    #pragma unroll
    for (int i = 0; i < 4; i++) v[i] = p[tid + i * 256];
    float m = fmaxf(fmaxf(v[0], v[1]), fmaxf(v[2], v[3]));
    __shared__ float sh[10];
    m = warp_max(m);
    int w = tid >> 5, l = tid & 31;
    if (!l) sh[w] = m;
    __syncthreads();
    if (tid == 0) {
        float t = sh[0];
        #pragma unroll
        for (int i = 1; i < 8; i++) t = fmaxf(t, sh[i]);
        sh[8] = t;
    }
    __syncthreads();
    m = sh[8];
    float s = 0.f;
    #pragma unroll
    for (int i = 0; i < 4; i++) { v[i] = __expf((v[i] - m) * scale); s += v[i]; }
    s = warp_sum(s);
    if (!l) sh[w] = s;
    __syncthreads();
    if (tid == 0) {
        float t = 0.f;
        #pragma unroll
        for (int i = 0; i < 8; i++) t += sh[i];
        sh[9] = 1.0f / t;
    }
    __syncthreads();
    float r = sh[9];
    #pragma unroll
    for (int i = 0; i < 4; i++) p[tid + i * 256] = v[i] * r;
}

// ---------------- transpose (batched) ----------------
__global__ __launch_bounds__(256)
void transpose_k(const float* __restrict__ in, int ldi, long soI, long siI,
                 float* __restrict__ out, int ldo, long soO, long siO, int zInner)
{
    __shared__ float t[32][33];
    int z = blockIdx.z, ob = z / zInner, ib = z - ob * zInner;
    in  += ob * soI + ib * siI;
    out += ob * soO + ib * siO;
    int c0 = blockIdx.x * 32, r0 = blockIdx.y * 32;
    int tx = threadIdx.x & 31, ty = threadIdx.x >> 5;
    #pragma unroll
    for (int i = ty; i < 32; i += 8)
        t[i][tx] = in[(long)(r0 + i) * ldi + c0 + tx];
    __syncthreads();
    #pragma unroll
    for (int i = ty; i < 32; i += 8)
        out[(long)(c0 + i) * ldo + r0 + tx] = t[tx][i];
}

// ---------------- TF32 mma.sync NT GEMM ----------------
// C[M,N] = A[M,K] @ B[N,K]^T.  Block tile BM x BN, BK = 32.
// 256 threads = 8 warps laid out WR x WC; warp tile (BM/WR) x (BN/WC).
// EPI: 0 store, 1 +bias+resid, 2 +bias then exact GELU.
#define PAD 36

template<int BM, int BN, int WR, int WC, int EPI>
__global__ __launch_bounds__(256)
void gemm_mma(const float* __restrict__ A, int lda, long soA, long siA,
              const float* __restrict__ B, int ldb, long soB, long siB,
              float* __restrict__ C, int ldc, long soC, long siC,
              int K, int zInner,
              const float* __restrict__ bias,
              const float* __restrict__ resid, int ldr)
{
    constexpr int BK = 32;
    constexpr int WM = BM / WR, WN = BN / WC;
    constexpr int MT = WM / 16, NT = WN / 8;
    constexpr int NA4 = BM / 32;      // float4 loads per thread for A tile
    constexpr int NB4 = BN / 32;
    constexpr int ASZ = BM * PAD;     // words per A buffer
    constexpr int BSZ = BN * PAD;

    extern __shared__ uint32_t sm[];
    uint32_t* As = sm;                // [2][BM][PAD]
    uint32_t* Bs = sm + 2 * ASZ;      // [2][BN][PAD]

    int tid = threadIdx.x, lane = tid & 31, wid = tid >> 5;
    int wr = wid / WC, wc = wid % WC;

    int z = blockIdx.z, ob = z / zInner, ib = z - ob * zInner;
    A += ob * soA + ib * siA;
    B += ob * soB + ib * siB;
    C += ob * soC + ib * siC;
    int m0 = blockIdx.y * BM, n0 = blockIdx.x * BN;

    const float* Ag = A + (long)m0 * lda;
    const float* Bg = B + (long)n0 * ldb;

    float acc[MT][NT][4];
    #pragma unroll
    for (int i = 0; i < MT; i++)
        #pragma unroll
        for (int j = 0; j < NT; j++)
            #pragma unroll
            for (int e = 0; e < 4; e++) acc[i][j][e] = 0.f;

    int arow[NA4], acol[NA4], brow[NB4], bcol[NB4];
    #pragma unroll
    for (int i = 0; i < NA4; i++) { int f = tid + i * 256; arow[i] = f >> 3; acol[i] = (f & 7) * 4; }
    #pragma unroll
    for (int i = 0; i < NB4; i++) { int f = tid + i * 256; brow[i] = f >> 3; bcol[i] = (f & 7) * 4; }

    // prologue: tile 0 -> smem buf 0
    {
        #pragma unroll
        for (int i = 0; i < NA4; i++) {
            float4 v = *reinterpret_cast<const float4*>(Ag + (long)arow[i] * lda + acol[i]);
            uint32_t* d = As + arow[i] * PAD + acol[i];
            d[0] = f2tf(v.x); d[1] = f2tf(v.y); d[2] = f2tf(v.z); d[3] = f2tf(v.w);
        }
        #pragma unroll
        for (int i = 0; i < NB4; i++) {
            float4 v = *reinterpret_cast<const float4*>(Bg + (long)brow[i] * ldb + bcol[i]);
            uint32_t* d = Bs + brow[i] * PAD + bcol[i];
            d[0] = f2tf(v.x); d[1] = f2tf(v.y); d[2] = f2tf(v.z); d[3] = f2tf(v.w);
        }
    }
    __syncthreads();

    int nCh = K >> 5;
    for (int c = 0; c < nCh; ++c) {
        int buf = c & 1;
        float4 pa[NA4], pb[NB4];
        if (c + 1 < nCh) {
            const float* An = Ag + (c + 1) * BK;
            const float* Bn = Bg + (c + 1) * BK;
            #pragma unroll
            for (int i = 0; i < NA4; i++)
                pa[i] = *reinterpret_cast<const float4*>(An + (long)arow[i] * lda + acol[i]);
            #pragma unroll
            for (int i = 0; i < NB4; i++)
                pb[i] = *reinterpret_cast<const float4*>(Bn + (long)brow[i] * ldb + bcol[i]);
        }

        const uint32_t* Ab = As + buf * ASZ + (wr * WM) * PAD;
        const uint32_t* Bb = Bs + buf * BSZ + (wc * WN) * PAD;
        int qr = lane >> 2, qc = lane & 3;

        #pragma unroll
        for (int ks = 0; ks < 4; ++ks) {
            int kk = ks * 8;
            uint32_t af[MT][4], bf[NT][2];
            #pragma unroll
            for (int mt = 0; mt < MT; mt++) {
                const uint32_t* p = Ab + (mt * 16 + qr) * PAD + kk + qc;
                af[mt][0] = p[0];
                af[mt][1] = p[8 * PAD];
                af[mt][2] = p[4];
                af[mt][3] = p[8 * PAD + 4];
            }
            #pragma unroll
            for (int nt = 0; nt < NT; nt++) {
                const uint32_t* p = Bb + (nt * 8 + qr) * PAD + kk + qc;
                bf[nt][0] = p[0];
                bf[nt][1] = p[4];
            }
            #pragma unroll
            for (int mt = 0; mt < MT; mt++)
                #pragma unroll
                for (int nt = 0; nt < NT; nt++)
                    mma_tf32(acc[mt][nt], af[mt], bf[nt]);
        }

        if (c + 1 < nCh) {
            uint32_t* Ad = As + (buf ^ 1) * ASZ;
            uint32_t* Bd = Bs + (buf ^ 1) * BSZ;
            #pragma unroll
            for (int i = 0; i < NA4; i++) {
                uint32_t* d = Ad + arow[i] * PAD + acol[i];
                d[0] = f2tf(pa[i].x); d[1] = f2tf(pa[i].y);
                d[2] = f2tf(pa[i].z); d[3] = f2tf(pa[i].w);
            }
            #pragma unroll
            for (int i = 0; i < NB4; i++) {
                uint32_t* d = Bd + brow[i] * PAD + bcol[i];
                d[0] = f2tf(pb[i].x); d[1] = f2tf(pb[i].y);
                d[2] = f2tf(pb[i].z); d[3] = f2tf(pb[i].w);
            }
        }
        __syncthreads();
    }

    // epilogue
    int qr = lane >> 2, qc = lane & 3;
    #pragma unroll
    for (int mt = 0; mt < MT; mt++) {
        #pragma unroll
        for (int half = 0; half < 2; half++) {
            int row = m0 + wr * WM + mt * 16 + qr + half * 8;
            float* Crow = C + (long)row * ldc;
            const float* Rrow = (EPI == 1) ? (resid + (long)row * ldr) : nullptr;
            #pragma unroll
            for (int nt = 0; nt < NT; nt++) {
                int col = n0 + wc * WN + nt * 8 + 2 * qc;
                float v0 = acc[mt][nt][half * 2 + 0];
                float v1 = acc[mt][nt][half * 2 + 1];
                if (EPI == 1) {
                    v0 += bias[col]     + Rrow[col];
                    v1 += bias[col + 1] + Rrow[col + 1];
                } else if (EPI == 2) {
                    v0 += bias[col];
                    v1 += bias[col + 1];
                    v0 = 0.5f * v0 * (1.0f + erff(v0 * 0.70710678118654752f));
                    v1 = 0.5f * v1 * (1.0f + erff(v1 * 0.70710678118654752f));
                }
                *reinterpret_cast<float2*>(&Crow[col]) = make_float2(v0, v1);
            }
        }
    }
}

// ---------------- launcher ----------------
extern "C" void kernel_launch(void* const* d_in, const int* in_sizes, int n_in,
                              void* d_out, int out_size)
{
    const float* x    = (const float*)d_in[0];
    const float* ln1g = (const float*)d_in[1];
    const float* ln1b = (const float*)d_in[2];
    const float* wq   = (const float*)d_in[3];
    const float* wk   = (const float*)d_in[4];
    const float* wv   = (const float*)d_in[5];
    const float* wo   = (const float*)d_in[6];
    const float* bo   = (const float*)d_in[7];
    const float* ln2g = (const float*)d_in[8];
    const float* ln2b = (const float*)d_in[9];
    const float* w1   = (const float*)d_in[10];
    const float* b1   = (const float*)d_in[11];
    const float* w2   = (const float*)d_in[12];
    const float* b2   = (const float*)d_in[13];
    float* out = (float*)d_out;

    float *xn, *qb, *kb, *vb, *vt, *attn, *x1, *hm, *sc, *w1t, *w2t;
    cudaGetSymbolAddress((void**)&xn,   g_xn);
    cudaGetSymbolAddress((void**)&qb,   g_q);
    cudaGetSymbolAddress((void**)&kb,   g_k);
    cudaGetSymbolAddress((void**)&vb,   g_v);
    cudaGetSymbolAddress((void**)&vt,   g_vt);
    cudaGetSymbolAddress((void**)&attn, g_attn);
    cudaGetSymbolAddress((void**)&x1,   g_x1);
    cudaGetSymbolAddress((void**)&hm,   g_h);
    cudaGetSymbolAddress((void**)&sc,   g_sc);
    cudaGetSymbolAddress((void**)&w1t,  g_w1t);
    cudaGetSymbolAddress((void**)&w2t,  g_w2t);

    // smem sizes (bytes): 2 buffers of (BM + BN) * PAD words
    const int SMLG = 2 * (128 + 128) * PAD * 4;   // 73728
    const int SMSM = 2 * (128 + 64)  * PAD * 4;   // 55296
    cudaFuncSetAttribute((const void*)gemm_mma<128,128,2,4,0>, cudaFuncAttributeMaxDynamicSharedMemorySize, SMLG);
    cudaFuncSetAttribute((const void*)gemm_mma<128,128,2,4,1>, cudaFuncAttributeMaxDynamicSharedMemorySize, SMLG);
    cudaFuncSetAttribute((const void*)gemm_mma<128,128,2,4,2>, cudaFuncAttributeMaxDynamicSharedMemorySize, SMLG);
    cudaFuncSetAttribute((const void*)gemm_mma<128,64,4,2,0>,  cudaFuncAttributeMaxDynamicSharedMemorySize, SMSM);

    const long sQA = (long)SEQ * HIDDEN;
    const long sQS = (long)HEADS * SEQ * SEQ;
    const long sHS = (long)SEQ * SEQ;
    const long sVT = (long)HEADS * HEAD_DIM * SEQ;
    const long sVTh = (long)HEAD_DIM * SEQ;

    // weight transposes
    transpose_k<<<dim3(MLPH / 32, HIDDEN / 32, 1), 256>>>(w1, MLPH, 0, 0, w1t, HIDDEN, 0, 0, 1);
    transpose_k<<<dim3(HIDDEN / 32, MLPH / 32, 1), 256>>>(w2, HIDDEN, 0, 0, w2t, MLPH, 0, 0, 1);

    // 1. LN1
    ln_k<<<MTOK, 256>>>(x, ln1g, ln1b, xn);

    // 2. QKV (M=16384, N=768, K=768) NT
    dim3 gQKV(HIDDEN / 128, MTOK / 128, 1);
    gemm_mma<128,128,2,4,0><<<gQKV, 256, SMLG>>>(xn, HIDDEN, 0, 0, wq, HIDDEN, 0, 0,
                                                 qb, HIDDEN, 0, 0, HIDDEN, 1, nullptr, nullptr, 0);
    gemm_mma<128,128,2,4,0><<<gQKV, 256, SMLG>>>(xn, HIDDEN, 0, 0, wk, HIDDEN, 0, 0,
                                                 kb, HIDDEN, 0, 0, HIDDEN, 1, nullptr, nullptr, 0);
    gemm_mma<128,128,2,4,0><<<gQKV, 256, SMLG>>>(xn, HIDDEN, 0, 0, wv, HIDDEN, 0, 0,
                                                 vb, HIDDEN, 0, 0, HIDDEN, 1, nullptr, nullptr, 0);

    // 3. V transpose per head
    transpose_k<<<dim3(HEAD_DIM / 32, SEQ / 32, BATCH * HEADS), 256>>>(
        vb, HIDDEN, sQA, HEAD_DIM, vt, SEQ, sVT, sVTh, HEADS);

    // 4. scores = Q @ K^T (M=N=1024, K=64, 192 heads)
    gemm_mma<128,128,2,4,0><<<dim3(SEQ / 128, SEQ / 128, BATCH * HEADS), 256, SMLG>>>(
        qb, HIDDEN, sQA, HEAD_DIM, kb, HIDDEN, sQA, HEAD_DIM,
        sc, SEQ, sQS, sHS, HEAD_DIM, HEADS, nullptr, nullptr, 0);

    // 5. softmax
    softmax_k<<<BATCH * HEADS * SEQ, 256>>>(sc);

    // 6. attn = P @ V (M=1024, N=64, K=1024)
    gemm_mma<128,64,4,2,0><<<dim3(1, SEQ / 128, BATCH * HEADS), 256, SMSM>>>(
        sc, SEQ, sQS, sHS, vt, SEQ, sVT, sVTh,
        attn, HIDDEN, sQA, HEAD_DIM, SEQ, HEADS, nullptr, nullptr, 0);

    // 7. x1 = attn @ wo^T + bo + x
    gemm_mma<128,128,2,4,1><<<gQKV, 256, SMLG>>>(attn, HIDDEN, 0, 0, wo, HIDDEN, 0, 0,
                                                 x1, HIDDEN, 0, 0, HIDDEN, 1, bo, x, HIDDEN);

    // 8. LN2
    ln_k<<<MTOK, 256>>>(x1, ln2g, ln2b, xn);

    // 9. h = gelu(xn @ w1 + b1)
    gemm_mma<128,128,2,4,2><<<dim3(MLPH / 128, MTOK / 128, 1), 256, SMLG>>>(
        xn, HIDDEN, 0, 0, w1t, HIDDEN, 0, 0, hm, MLPH, 0, 0, HIDDEN, 1, b1, nullptr, 0);

    // 10. out = h @ w2 + b2 + x1
    gemm_mma<128,128,2,4,1><<<gQKV, 256, SMLG>>>(hm, MLPH, 0, 0, w2t, MLPH, 0, 0,
                                                 out, HIDDEN, 0, 0, MLPH, 1, b2, x1, HIDDEN);
}

// round 4
// speedup vs baseline: 2.6931x; 1.1244x over previous
#include <cuda_runtime.h>
#include <math.h>
#include <stdint.h>

// ---------------- problem constants ----------------
#define HIDDEN   768
#define MLPH     3072
#define HEADS    12
#define HEAD_DIM 64
#define BATCH    16
#define SEQ      1024
#define MTOK     (BATCH * SEQ)

// ---------------- scratch (device globals; no allocation) ----------------
__device__ float g_xn  [(size_t)MTOK * HIDDEN];
__device__ float g_q   [(size_t)MTOK * HIDDEN];
__device__ float g_k   [(size_t)MTOK * HIDDEN];
__device__ float g_v   [(size_t)MTOK * HIDDEN];
__device__ float g_vt  [(size_t)BATCH * HEADS * HEAD_DIM * SEQ];
__device__ float g_attn[(size_t)MTOK * HIDDEN];
__device__ float g_x1  [(size_t)MTOK * HIDDEN];
__device__ float g_h   [(size_t)MTOK * MLPH];
__device__ float g_sc  [(size_t)BATCH * HEADS * SEQ * SEQ];
__device__ float g_w1t [(size_t)MLPH * HIDDEN];
__device__ float g_w2t [(size_t)HIDDEN * MLPH];

// ---------------- helpers ----------------
__device__ __forceinline__ uint32_t f2tf(float f) {
    uint32_t r; asm("cvt.rna.tf32.f32 %0, %1;" : "=r"(r) : "f"(f)); return r;
}
__device__ __forceinline__ void mma_tf32(float* d, const uint32_t* a, const uint32_t* b) {
    asm volatile("mma.sync.aligned.m16n8k8.row.col.f32.tf32.tf32.f32 "
                 "{%0,%1,%2,%3}, {%4,%5,%6,%7}, {%8,%9}, {%0,%1,%2,%3};"
                 : "+f"(d[0]), "+f"(d[1]), "+f"(d[2]), "+f"(d[3])
                 : "r"(a[0]), "r"(a[1]), "r"(a[2]), "r"(a[3]), "r"(b[0]), "r"(b[1]));
}
__device__ __forceinline__ float warp_sum(float v) {
    #pragma unroll
    for (int o = 16; o; o >>= 1) v += __shfl_xor_sync(0xffffffffu, v, o);
    return v;
}
__device__ __forceinline__ float warp_max(float v) {
    #pragma unroll
    for (int o = 16; o; o >>= 1) v = fmaxf(v, __shfl_xor_sync(0xffffffffu, v, o));
    return v;
}

// ---------------- LayerNorm ----------------
__global__ __launch_bounds__(256)
void ln_k(const float* __restrict__ x, const float* __restrict__ g,
          const float* __restrict__ b, float* __restrict__ out)
{
    long row = blockIdx.x;
    const float* xr = x + row * (long)HIDDEN;
    int tid = threadIdx.x;
    float v0 = xr[tid], v1 = xr[tid + 256], v2 = xr[tid + 512];
    float s  = v0 + v1 + v2;
    float s2 = v0 * v0 + v1 * v1 + v2 * v2;
    __shared__ float sh[18];
    s = warp_sum(s); s2 = warp_sum(s2);
    int w = tid >> 5, l = tid & 31;
    if (!l) { sh[w] = s; sh[w + 8] = s2; }
    __syncthreads();
    if (tid == 0) {
        float ts = 0.f, ts2 = 0.f;
        #pragma unroll
        for (int i = 0; i < 8; i++) { ts += sh[i]; ts2 += sh[i + 8]; }
        float mu  = ts * (1.0f / HIDDEN);
        float var = ts2 * (1.0f / HIDDEN) - mu * mu;
        sh[16] = mu; sh[17] = rsqrtf(var + 1e-5f);
    }
    __syncthreads();
    float mu = sh[16], inv = sh[17];
    float* o = out + row * (long)HIDDEN;
    o[tid]       = (v0 - mu) * inv * g[tid]       + b[tid];
    o[tid + 256] = (v1 - mu) * inv * g[tid + 256] + b[tid + 256];
    o[tid + 512] = (v2 - mu) * inv * g[tid + 512] + b[tid + 512];
}

// ---------------- softmax (scale folded in) ----------------
__global__ __launch_bounds__(256)
void softmax_k(float* __restrict__ sc)
{
    long row = blockIdx.x;
    float* p = sc + row * (long)SEQ;
    int tid = threadIdx.x;
    const float scale = 0.125f;
    float v[4];
    #pragma unroll
    for (int i = 0; i < 4; i++) v[i] = p[tid + i * 256];
    float m = fmaxf(fmaxf(v[0], v[1]), fmaxf(v[2], v[3]));
    __shared__ float sh[10];
    m = warp_max(m);
    int w = tid >> 5, l = tid & 31;
    if (!l) sh[w] = m;
    __syncthreads();
    if (tid == 0) {
        float t = sh[0];
        #pragma unroll
        for (int i = 1; i < 8; i++) t = fmaxf(t, sh[i]);
        sh[8] = t;
    }
    __syncthreads();
    m = sh[8];
    float s = 0.f;
    #pragma unroll
    for (int i = 0; i < 4; i++) { v[i] = __expf((v[i] - m) * scale); s += v[i]; }
    s = warp_sum(s);
    if (!l) sh[w] = s;
    __syncthreads();
    if (tid == 0) {
        float t = 0.f;
        #pragma unroll
        for (int i = 0; i < 8; i++) t += sh[i];
        sh[9] = 1.0f / t;
    }
    __syncthreads();
    float r = sh[9];
    #pragma unroll
    for (int i = 0; i < 4; i++) p[tid + i * 256] = v[i] * r;
}

// ---------------- transpose (batched) ----------------
__global__ __launch_bounds__(256)
void transpose_k(const float* __restrict__ in, int ldi, long soI, long siI,
                 float* __restrict__ out, int ldo, long soO, long siO, int zInner)
{
    __shared__ float t[32][33];
    int z = blockIdx.z, ob = z / zInner, ib = z - ob * zInner;
    in  += ob * soI + ib * siI;
    out += ob * soO + ib * siO;
    int c0 = blockIdx.x * 32, r0 = blockIdx.y * 32;
    int tx = threadIdx.x & 31, ty = threadIdx.x >> 5;
    #pragma unroll
    for (int i = ty; i < 32; i += 8)
        t[i][tx] = in[(long)(r0 + i) * ldi + c0 + tx];
    __syncthreads();
    #pragma unroll
    for (int i = ty; i < 32; i += 8)
        out[(long)(c0 + i) * ldo + r0 + tx] = t[tx][i];
}

// ---------------- TF32 mma.sync NT GEMM ----------------
// C[M,N] = A[M,K] @ B[N,K]^T.  Block tile BM x BN, BK = 32.
// 256 threads = 8 warps laid out WR x WC; warp tile (BM/WR) x (BN/WC).
// EPI: 0 store, 1 +bias+resid, 2 +bias then exact GELU.
#define PAD 36

template<int BM, int BN, int WR, int WC, int EPI>
__global__ __launch_bounds__(256)
void gemm_mma(const float* __restrict__ A, int lda, long soA, long siA,
              const float* __restrict__ B, int ldb, long soB, long siB,
              float* __restrict__ C, int ldc, long soC, long siC,
              int K, int zInner,
              const float* __restrict__ bias,
              const float* __restrict__ resid, int ldr)
{
    constexpr int BK = 32;
    constexpr int WM = BM / WR, WN = BN / WC;
    constexpr int MT = WM / 16, NT = WN / 8;
    constexpr int NA4 = BM / 32;
    constexpr int NB4 = BN / 32;
    constexpr int ASZ = BM * PAD;
    constexpr int BSZ = BN * PAD;

    extern __shared__ uint32_t sm[];
    uint32_t* As = sm;                // [2][BM][PAD]
    uint32_t* Bs = sm + 2 * ASZ;      // [2][BN][PAD]

    int tid = threadIdx.x, lane = tid & 31, wid = tid >> 5;
    int wr = wid / WC, wc = wid % WC;

    int z = blockIdx.z, ob = z / zInner, ib = z - ob * zInner;
    A += ob * soA + ib * siA;
    B += ob * soB + ib * siB;
    C += ob * soC + ib * siC;
    int m0 = blockIdx.y * BM, n0 = blockIdx.x * BN;

    const float* Ag = A + (long)m0 * lda;
    const float* Bg = B + (long)n0 * ldb;

    float acc[MT][NT][4];
    #pragma unroll
    for (int i = 0; i < MT; i++)
        #pragma unroll
        for (int j = 0; j < NT; j++)
            #pragma unroll
            for (int e = 0; e < 4; e++) acc[i][j][e] = 0.f;

    int arow[NA4], acol[NA4], brow[NB4], bcol[NB4];
    #pragma unroll
    for (int i = 0; i < NA4; i++) { int f = tid + i * 256; arow[i] = f >> 3; acol[i] = (f & 7) * 4; }
    #pragma unroll
    for (int i = 0; i < NB4; i++) { int f = tid + i * 256; brow[i] = f >> 3; bcol[i] = (f & 7) * 4; }

    // prologue: tile 0 -> smem buf 0
    {
        #pragma unroll
        for (int i = 0; i < NA4; i++) {
            float4 v = *reinterpret_cast<const float4*>(Ag + (long)arow[i] * lda + acol[i]);
            uint32_t* d = As + arow[i] * PAD + acol[i];
            d[0] = f2tf(v.x); d[1] = f2tf(v.y); d[2] = f2tf(v.z); d[3] = f2tf(v.w);
        }
        #pragma unroll
        for (int i = 0; i < NB4; i++) {
            float4 v = *reinterpret_cast<const float4*>(Bg + (long)brow[i] * ldb + bcol[i]);
            uint32_t* d = Bs + brow[i] * PAD + bcol[i];
            d[0] = f2tf(v.x); d[1] = f2tf(v.y); d[2] = f2tf(v.z); d[3] = f2tf(v.w);
        }
    }
    __syncthreads();

    int nCh = K >> 5;
    for (int c = 0; c < nCh; ++c) {
        int buf = c & 1;
        float4 pa[NA4], pb[NB4];
        if (c + 1 < nCh) {
            const float* An = Ag + (c + 1) * BK;
            const float* Bn = Bg + (c + 1) * BK;
            #pragma unroll
            for (int i = 0; i < NA4; i++)
                pa[i] = *reinterpret_cast<const float4*>(An + (long)arow[i] * lda + acol[i]);
            #pragma unroll
            for (int i = 0; i < NB4; i++)
                pb[i] = *reinterpret_cast<const float4*>(Bn + (long)brow[i] * ldb + bcol[i]);
        }

        const uint32_t* Ab = As + buf * ASZ + (wr * WM) * PAD;
        const uint32_t* Bb = Bs + buf * BSZ + (wc * WN) * PAD;
        int qr = lane >> 2, qc = lane & 3;

        #pragma unroll
        for (int ks = 0; ks < 4; ++ks) {
            int kk = ks * 8;
            uint32_t af[MT][4], bf[NT][2];
            #pragma unroll
            for (int mt = 0; mt < MT; mt++) {
                const uint32_t* p = Ab + (mt * 16 + qr) * PAD + kk + qc;
                af[mt][0] = p[0];
                af[mt][1] = p[8 * PAD];
                af[mt][2] = p[4];
                af[mt][3] = p[8 * PAD + 4];
            }
            #pragma unroll
            for (int nt = 0; nt < NT; nt++) {
                const uint32_t* p = Bb + (nt * 8 + qr) * PAD + kk + qc;
                bf[nt][0] = p[0];
                bf[nt][1] = p[4];
            }
            #pragma unroll
            for (int mt = 0; mt < MT; mt++)
                #pragma unroll
                for (int nt = 0; nt < NT; nt++)
                    mma_tf32(acc[mt][nt], af[mt], bf[nt]);
        }

        if (c + 1 < nCh) {
            uint32_t* Ad = As + (buf ^ 1) * ASZ;
            uint32_t* Bd = Bs + (buf ^ 1) * BSZ;
            #pragma unroll
            for (int i = 0; i < NA4; i++) {
                uint32_t* d = Ad + arow[i] * PAD + acol[i];
                d[0] = f2tf(pa[i].x); d[1] = f2tf(pa[i].y);
                d[2] = f2tf(pa[i].z); d[3] = f2tf(pa[i].w);
            }
            #pragma unroll
            for (int i = 0; i < NB4; i++) {
                uint32_t* d = Bd + brow[i] * PAD + bcol[i];
                d[0] = f2tf(pb[i].x); d[1] = f2tf(pb[i].y);
                d[2] = f2tf(pb[i].z); d[3] = f2tf(pb[i].w);
            }
        }
        __syncthreads();
    }

    // epilogue
    int qr = lane >> 2, qc = lane & 3;
    #pragma unroll
    for (int mt = 0; mt < MT; mt++) {
        #pragma unroll
        for (int half = 0; half < 2; half++) {
            int row = m0 + wr * WM + mt * 16 + qr + half * 8;
            float* Crow = C + (long)row * ldc;
            const float* Rrow = (EPI == 1) ? (resid + (long)row * ldr) : nullptr;
            #pragma unroll
            for (int nt = 0; nt < NT; nt++) {
                int col = n0 + wc * WN + nt * 8 + 2 * qc;
                float v0 = acc[mt][nt][half * 2 + 0];
                float v1 = acc[mt][nt][half * 2 + 1];
                if (EPI == 1) {
                    v0 += bias[col]     + Rrow[col];
                    v1 += bias[col + 1] + Rrow[col + 1];
                } else if (EPI == 2) {
                    v0 += bias[col];
                    v1 += bias[col + 1];
                    v0 = 0.5f * v0 * (1.0f + erff(v0 * 0.70710678118654752f));
                    v1 = 0.5f * v1 * (1.0f + erff(v1 * 0.70710678118654752f));
                }
                *reinterpret_cast<float2*>(&Crow[col]) = make_float2(v0, v1);
            }
        }
    }
}

// ---------------- launcher ----------------
extern "C" void kernel_launch(void* const* d_in, const int* in_sizes, int n_in,
                              void* d_out, int out_size)
{
    const float* x    = (const float*)d_in[0];
    const float* ln1g = (const float*)d_in[1];
    const float* ln1b = (const float*)d_in[2];
    const float* wq   = (const float*)d_in[3];
    const float* wk   = (const float*)d_in[4];
    const float* wv   = (const float*)d_in[5];
    const float* wo   = (const float*)d_in[6];
    const float* bo   = (const float*)d_in[7];
    const float* ln2g = (const float*)d_in[8];
    const float* ln2b = (const float*)d_in[9];
    const float* w1   = (const float*)d_in[10];
    const float* b1   = (const float*)d_in[11];
    const float* w2   = (const float*)d_in[12];
    const float* b2   = (const float*)d_in[13];
    float* out = (float*)d_out;

    float *xn, *qb, *kb, *vb, *vt, *attn, *x1, *hm, *sc, *w1t, *w2t;
    cudaGetSymbolAddress((void**)&xn,   g_xn);
    cudaGetSymbolAddress((void**)&qb,   g_q);
    cudaGetSymbolAddress((void**)&kb,   g_k);
    cudaGetSymbolAddress((void**)&vb,   g_v);
    cudaGetSymbolAddress((void**)&vt,   g_vt);
    cudaGetSymbolAddress((void**)&attn, g_attn);
    cudaGetSymbolAddress((void**)&x1,   g_x1);
    cudaGetSymbolAddress((void**)&hm,   g_h);
    cudaGetSymbolAddress((void**)&sc,   g_sc);
    cudaGetSymbolAddress((void**)&w1t,  g_w1t);
    cudaGetSymbolAddress((void**)&w2t,  g_w2t);

    // smem (bytes): 2 buffers of (BM + BN) * PAD words
    const int SMLG = 2 * (128 + 256) * PAD * 4;   // 110592
    const int SMSM = 2 * (128 + 64)  * PAD * 4;   // 55296
    cudaFuncSetAttribute((const void*)gemm_mma<128,256,2,4,0>, cudaFuncAttributeMaxDynamicSharedMemorySize, SMLG);
    cudaFuncSetAttribute((const void*)gemm_mma<128,256,2,4,1>, cudaFuncAttributeMaxDynamicSharedMemorySize, SMLG);
    cudaFuncSetAttribute((const void*)gemm_mma<128,256,2,4,2>, cudaFuncAttributeMaxDynamicSharedMemorySize, SMLG);
    cudaFuncSetAttribute((const void*)gemm_mma<128,64,4,2,0>,  cudaFuncAttributeMaxDynamicSharedMemorySize, SMSM);

    const long sQA = (long)SEQ * HIDDEN;
    const long sQS = (long)HEADS * SEQ * SEQ;
    const long sHS = (long)SEQ * SEQ;
    const long sVT = (long)HEADS * HEAD_DIM * SEQ;
    const long sVTh = (long)HEAD_DIM * SEQ;

    // weight transposes
    transpose_k<<<dim3(MLPH / 32, HIDDEN / 32, 1), 256>>>(w1, MLPH, 0, 0, w1t, HIDDEN, 0, 0, 1);
    transpose_k<<<dim3(HIDDEN / 32, MLPH / 32, 1), 256>>>(w2, HIDDEN, 0, 0, w2t, MLPH, 0, 0, 1);

    // 1. LN1
    ln_k<<<MTOK, 256>>>(x, ln1g, ln1b, xn);

    // 2. QKV (M=16384, N=768, K=768) NT
    dim3 gQKV(HIDDEN / 256, MTOK / 128, 1);
    gemm_mma<128,256,2,4,0><<<gQKV, 256, SMLG>>>(xn, HIDDEN, 0, 0, wq, HIDDEN, 0, 0,
                                                 qb, HIDDEN, 0, 0, HIDDEN, 1, nullptr, nullptr, 0);
    gemm_mma<128,256,2,4,0><<<gQKV, 256, SMLG>>>(xn, HIDDEN, 0, 0, wk, HIDDEN, 0, 0,
                                                 kb, HIDDEN, 0, 0, HIDDEN, 1, nullptr, nullptr, 0);
    gemm_mma<128,256,2,4,0><<<gQKV, 256, SMLG>>>(xn, HIDDEN, 0, 0, wv, HIDDEN, 0, 0,
                                                 vb, HIDDEN, 0, 0, HIDDEN, 1, nullptr, nullptr, 0);

    // 3. V transpose per head
    transpose_k<<<dim3(HEAD_DIM / 32, SEQ / 32, BATCH * HEADS), 256>>>(
        vb, HIDDEN, sQA, HEAD_DIM, vt, SEQ, sVT, sVTh, HEADS);

    // 4. scores = Q @ K^T (M=N=1024, K=64, 192 heads)
    gemm_mma<128,256,2,4,0><<<dim3(SEQ / 256, SEQ / 128, BATCH * HEADS), 256, SMLG>>>(
        qb, HIDDEN, sQA, HEAD_DIM, kb, HIDDEN, sQA, HEAD_DIM,
        sc, SEQ, sQS, sHS, HEAD_DIM, HEADS, nullptr, nullptr, 0);

    // 5. softmax
    softmax_k<<<BATCH * HEADS * SEQ, 256>>>(sc);

    // 6. attn = P @ V (M=1024, N=64, K=1024)
    gemm_mma<128,64,4,2,0><<<dim3(1, SEQ / 128, BATCH * HEADS), 256, SMSM>>>(
        sc, SEQ, sQS, sHS, vt, SEQ, sVT, sVTh,
        attn, HIDDEN, sQA, HEAD_DIM, SEQ, HEADS, nullptr, nullptr, 0);

    // 7. x1 = attn @ wo^T + bo + x
    gemm_mma<128,256,2,4,1><<<gQKV, 256, SMLG>>>(attn, HIDDEN, 0, 0, wo, HIDDEN, 0, 0,
                                                 x1, HIDDEN, 0, 0, HIDDEN, 1, bo, x, HIDDEN);

    // 8. LN2
    ln_k<<<MTOK, 256>>>(x1, ln2g, ln2b, xn);

    // 9. h = gelu(xn @ w1 + b1)
    gemm_mma<128,256,2,4,2><<<dim3(MLPH / 256, MTOK / 128, 1), 256, SMLG>>>(
        xn, HIDDEN, 0, 0, w1t, HIDDEN, 0, 0, hm, MLPH, 0, 0, HIDDEN, 1, b1, nullptr, 0);

    // 10. out = h @ w2 + b2 + x1
    gemm_mma<128,256,2,4,1><<<gQKV, 256, SMLG>>>(hm, MLPH, 0, 0, w2t, MLPH, 0, 0,
                                                 out, HIDDEN, 0, 0, MLPH, 1, b2, x1, HIDDEN);
}

// round 5
// speedup vs baseline: 3.2180x; 1.1949x over previous
#include <cuda_runtime.h>
#include <math.h>
#include <stdint.h>

// ---------------- problem constants ----------------
#define HIDDEN   768
#define MLPH     3072
#define HEADS    12
#define HEAD_DIM 64
#define BATCH    16
#define SEQ      1024
#define MTOK     (BATCH * SEQ)

// ---------------- scratch (device globals; no allocation) ----------------
__device__ float g_xn  [(size_t)MTOK * HIDDEN];
__device__ float g_q   [(size_t)MTOK * HIDDEN];
__device__ float g_k   [(size_t)MTOK * HIDDEN];
__device__ float g_v   [(size_t)MTOK * HIDDEN];
__device__ float g_attn[(size_t)MTOK * HIDDEN];
__device__ float g_x1  [(size_t)MTOK * HIDDEN];
__device__ float g_h   [(size_t)MTOK * MLPH];
__device__ float g_w1t [(size_t)MLPH * HIDDEN];
__device__ float g_w2t [(size_t)HIDDEN * MLPH];

// ---------------- helpers ----------------
__device__ __forceinline__ uint32_t f2tf(float f) {
    uint32_t r; asm("cvt.rna.tf32.f32 %0, %1;" : "=r"(r) : "f"(f)); return r;
}
__device__ __forceinline__ void mma_tf32(float* d, const uint32_t* a, const uint32_t* b) {
    asm volatile("mma.sync.aligned.m16n8k8.row.col.f32.tf32.tf32.f32 "
                 "{%0,%1,%2,%3}, {%4,%5,%6,%7}, {%8,%9}, {%0,%1,%2,%3};"
                 : "+f"(d[0]), "+f"(d[1]), "+f"(d[2]), "+f"(d[3])
                 : "r"(a[0]), "r"(a[1]), "r"(a[2]), "r"(a[3]), "r"(b[0]), "r"(b[1]));
}
__device__ __forceinline__ float warp_sum(float v) {
    #pragma unroll
    for (int o = 16; o; o >>= 1) v += __shfl_xor_sync(0xffffffffu, v, o);
    return v;
}
__device__ __forceinline__ float warp_max(float v) {
    #pragma unroll
    for (int o = 16; o; o >>= 1) v = fmaxf(v, __shfl_xor_sync(0xffffffffu, v, o));
    return v;
}

// ---------------- LayerNorm ----------------
__global__ __launch_bounds__(256)
void ln_k(const float* __restrict__ x, const float* __restrict__ g,
          const float* __restrict__ b, float* __restrict__ out)
{
    long row = blockIdx.x;
    const float* xr = x + row * (long)HIDDEN;
    int tid = threadIdx.x;
    float v0 = xr[tid], v1 = xr[tid + 256], v2 = xr[tid + 512];
    float s  = v0 + v1 + v2;
    float s2 = v0 * v0 + v1 * v1 + v2 * v2;
    __shared__ float sh[18];
    s = warp_sum(s); s2 = warp_sum(s2);
    int w = tid >> 5, l = tid & 31;
    if (!l) { sh[w] = s; sh[w + 8] = s2; }
    __syncthreads();
    if (tid == 0) {
        float ts = 0.f, ts2 = 0.f;
        #pragma unroll
        for (int i = 0; i < 8; i++) { ts += sh[i]; ts2 += sh[i + 8]; }
        float mu  = ts * (1.0f / HIDDEN);
        float var = ts2 * (1.0f / HIDDEN) - mu * mu;
        sh[16] = mu; sh[17] = rsqrtf(var + 1e-5f);
    }
    __syncthreads();
    float mu = sh[16], inv = sh[17];
    float* o = out + row * (long)HIDDEN;
    o[tid]       = (v0 - mu) * inv * g[tid]       + b[tid];
    o[tid + 256] = (v1 - mu) * inv * g[tid + 256] + b[tid + 256];
    o[tid + 512] = (v2 - mu) * inv * g[tid + 512] + b[tid + 512];
}

// ---------------- transpose (weights) ----------------
__global__ __launch_bounds__(256)
void transpose_k(const float* __restrict__ in, int ldi,
                 float* __restrict__ out, int ldo)
{
    __shared__ float t[32][33];
    int c0 = blockIdx.x * 32, r0 = blockIdx.y * 32;
    int tx = threadIdx.x & 31, ty = threadIdx.x >> 5;
    #pragma unroll
    for (int i = ty; i < 32; i += 8)
        t[i][tx] = in[(long)(r0 + i) * ldi + c0 + tx];
    __syncthreads();
    #pragma unroll
    for (int i = ty; i < 32; i += 8)
        out[(long)(c0 + i) * ldo + r0 + tx] = t[tx][i];
}

// ---------------- flash attention ----------------
// One CTA per (q-tile of 128, b*h). 8 warps x 16 q-rows.
// Loops over 8 key-chunks of 128: S = Q@K^T (tf32 mma), online softmax,
// O += P@V with P converted accum->A-frag layout via intra-quad shuffles.
#define FPK 68    // Ks/Qs row stride (words)
#define FPV 133   // Vs row stride (words)

__global__ __launch_bounds__(256)
void flash_k(const float* __restrict__ Q, const float* __restrict__ Kg,
             const float* __restrict__ Vg, float* __restrict__ Og)
{
    extern __shared__ uint32_t sm[];
    uint32_t* Qs = sm;                     // [128][FPK]
    uint32_t* Ks = sm + 128 * FPK;         // [128][FPK]
    uint32_t* Vs = sm + 2 * 128 * FPK;     // [64][FPV]  (V transposed: [dim][key])

    int tid = threadIdx.x, lane = tid & 31, wid = tid >> 5;
    int qr = lane >> 2, qc = lane & 3;
    int z = blockIdx.y;                    // b*HEADS + h
    int b = z / HEADS, h = z - b * HEADS;
    int q0 = blockIdx.x * 128;
    long tokbase = (long)b * SEQ + q0;

    const float* Qp = Q  + tokbase * HIDDEN + h * HEAD_DIM;
    const float* Kp = Kg + (long)b * SEQ * HIDDEN + h * HEAD_DIM;
    const float* Vp = Vg + (long)b * SEQ * HIDDEN + h * HEAD_DIM;

    // stage Q tile (128x64) as tf32
    #pragma unroll
    for (int i = 0; i < 8; i++) {
        int idx = tid + i * 256; int t = idx >> 4, c = idx & 15;
        float4 v = *reinterpret_cast<const float4*>(Qp + (long)t * HIDDEN + c * 4);
        uint32_t* d = Qs + t * FPK + c * 4;
        d[0] = f2tf(v.x); d[1] = f2tf(v.y); d[2] = f2tf(v.z); d[3] = f2tf(v.w);
    }
    __syncthreads();

    // persistent Q fragments (warp rows = wid*16 .. +15)
    uint32_t qf[8][4];
    {
        const uint32_t* Wq = Qs + (wid * 16 + qr) * FPK;
        #pragma unroll
        for (int ks = 0; ks < 8; ks++) {
            const uint32_t* p = Wq + ks * 8 + qc;
            qf[ks][0] = p[0]; qf[ks][1] = p[8 * FPK];
            qf[ks][2] = p[4]; qf[ks][3] = p[8 * FPK + 4];
        }
    }

    float oa[8][4];
    #pragma unroll
    for (int i = 0; i < 8; i++)
        #pragma unroll
        for (int e = 0; e < 4; e++) oa[i][e] = 0.f;
    float mA = -1e30f, mB = -1e30f, lA = 0.f, lB = 0.f;
    const float scale = 0.125f;

    for (int ch = 0; ch < SEQ / 128; ch++) {
        __syncthreads();   // protect Ks/Vs from previous iteration's readers
        const float* Kc = Kp + (long)ch * 128 * HIDDEN;
        const float* Vc = Vp + (long)ch * 128 * HIDDEN;
        #pragma unroll
        for (int i = 0; i < 8; i++) {
            int idx = tid + i * 256; int t = idx >> 4, c = idx & 15;
            float4 v = *reinterpret_cast<const float4*>(Kc + (long)t * HIDDEN + c * 4);
            uint32_t* d = Ks + t * FPK + c * 4;
            d[0] = f2tf(v.x); d[1] = f2tf(v.y); d[2] = f2tf(v.z); d[3] = f2tf(v.w);
        }
        #pragma unroll
        for (int i = 0; i < 8; i++) {
            int idx = tid + i * 256; int t = idx >> 4, c = idx & 15;
            float4 v = *reinterpret_cast<const float4*>(Vc + (long)t * HIDDEN + c * 4);
            Vs[(4 * c + 0) * FPV + t] = f2tf(v.x);
            Vs[(4 * c + 1) * FPV + t] = f2tf(v.y);
            Vs[(4 * c + 2) * FPV + t] = f2tf(v.z);
            Vs[(4 * c + 3) * FPV + t] = f2tf(v.w);
        }
        __syncthreads();

        // S = Q @ K^T : warp tile 16 x 128
        float sa[16][4];
        #pragma unroll
        for (int i = 0; i < 16; i++)
            #pragma unroll
            for (int e = 0; e < 4; e++) sa[i][e] = 0.f;
        #pragma unroll
        for (int ks = 0; ks < 8; ks++) {
            #pragma unroll
            for (int nt = 0; nt < 16; nt++) {
                const uint32_t* p = Ks + (nt * 8 + qr) * FPK + ks * 8 + qc;
                uint32_t bf[2] = { p[0], p[4] };
                mma_tf32(sa[nt], qf[ks], bf);
            }
        }

        // online softmax (rows r = lane>>2 and r+8 per thread)
        float rmA = -1e30f, rmB = -1e30f;
        #pragma unroll
        for (int nt = 0; nt < 16; nt++) {
            rmA = fmaxf(rmA, fmaxf(sa[nt][0], sa[nt][1]));
            rmB = fmaxf(rmB, fmaxf(sa[nt][2], sa[nt][3]));
        }
        rmA = fmaxf(rmA, __shfl_xor_sync(0xffffffffu, rmA, 1));
        rmA = fmaxf(rmA, __shfl_xor_sync(0xffffffffu, rmA, 2));
        rmB = fmaxf(rmB, __shfl_xor_sync(0xffffffffu, rmB, 1));
        rmB = fmaxf(rmB, __shfl_xor_sync(0xffffffffu, rmB, 2));
        float mAn = fmaxf(mA, rmA), mBn = fmaxf(mB, rmB);
        float aA = __expf((mA - mAn) * scale), aB = __expf((mB - mBn) * scale);
        float sA = 0.f, sB = 0.f;
        #pragma unroll
        for (int nt = 0; nt < 16; nt++) {
            sa[nt][0] = __expf((sa[nt][0] - mAn) * scale);
            sa[nt][1] = __expf((sa[nt][1] - mAn) * scale);
            sa[nt][2] = __expf((sa[nt][2] - mBn) * scale);
            sa[nt][3] = __expf((sa[nt][3] - mBn) * scale);
            sA += sa[nt][0] + sa[nt][1];
            sB += sa[nt][2] + sa[nt][3];
        }
        sA += __shfl_xor_sync(0xffffffffu, sA, 1);
        sA += __shfl_xor_sync(0xffffffffu, sA, 2);
        sB += __shfl_xor_sync(0xffffffffu, sB, 1);
        sB += __shfl_xor_sync(0xffffffffu, sB, 2);
        lA = aA * lA + sA;  lB = aB * lB + sB;
        mA = mAn;  mB = mBn;
        #pragma unroll
        for (int nt = 0; nt < 8; nt++) {
            oa[nt][0] *= aA; oa[nt][1] *= aA;
            oa[nt][2] *= aB; oa[nt][3] *= aB;
        }

        // O += P @ V  (P accum frags -> A frags via intra-quad shuffles)
        int s0 = (lane & ~3) | (qc >> 1);
        int s1 = s0 + 2;
        bool hi = qc & 1;
        #pragma unroll
        for (int kk = 0; kk < 16; kk++) {
            uint32_t p0 = f2tf(sa[kk][0]), p1 = f2tf(sa[kk][1]);
            uint32_t p2 = f2tf(sa[kk][2]), p3 = f2tf(sa[kk][3]);
            uint32_t u0 = __shfl_sync(0xffffffffu, p0, s0);
            uint32_t u1 = __shfl_sync(0xffffffffu, p1, s0);
            uint32_t v0 = __shfl_sync(0xffffffffu, p2, s0);
            uint32_t v1 = __shfl_sync(0xffffffffu, p3, s0);
            uint32_t w0 = __shfl_sync(0xffffffffu, p0, s1);
            uint32_t w1 = __shfl_sync(0xffffffffu, p1, s1);
            uint32_t x0 = __shfl_sync(0xffffffffu, p2, s1);
            uint32_t x1 = __shfl_sync(0xffffffffu, p3, s1);
            uint32_t af[4];
            af[0] = hi ? u1 : u0;  af[1] = hi ? v1 : v0;
            af[2] = hi ? w1 : w0;  af[3] = hi ? x1 : x0;
            #pragma unroll
            for (int nt = 0; nt < 8; nt++) {
                const uint32_t* p = Vs + (nt * 8 + qr) * FPV + kk * 8 + qc;
                uint32_t bf[2] = { p[0], p[4] };
                mma_tf32(oa[nt], af, bf);
            }
        }
    }

    // epilogue: O /= l, write [token][h*64 + dim]
    float rA = 1.f / lA, rB = 1.f / lB;
    long rowA = tokbase + wid * 16 + qr;
    float* OA = Og + rowA * HIDDEN + h * HEAD_DIM;
    float* OB = OA + 8 * HIDDEN;
    #pragma unroll
    for (int nt = 0; nt < 8; nt++) {
        int col = nt * 8 + 2 * qc;
        *reinterpret_cast<float2*>(OA + col) = make_float2(oa[nt][0] * rA, oa[nt][1] * rA);
        *reinterpret_cast<float2*>(OB + col) = make_float2(oa[nt][2] * rB, oa[nt][3] * rB);
    }
}

// ---------------- TF32 mma.sync NT GEMM (unchanged from R4) ----------------
#define PAD 36

template<int BM, int BN, int WR, int WC, int EPI>
__global__ __launch_bounds__(256)
void gemm_mma(const float* __restrict__ A, int lda,
              const float* __restrict__ B, int ldb,
              float* __restrict__ C, int ldc,
              int K,
              const float* __restrict__ bias,
              const float* __restrict__ resid, int ldr)
{
    constexpr int BK = 32;
    constexpr int WM = BM / WR, WN = BN / WC;
    constexpr int MT = WM / 16, NT = WN / 8;
    constexpr int NA4 = BM / 32;
    constexpr int NB4 = BN / 32;
    constexpr int ASZ = BM * PAD;
    constexpr int BSZ = BN * PAD;

    extern __shared__ uint32_t sm[];
    uint32_t* As = sm;
    uint32_t* Bs = sm + 2 * ASZ;

    int tid = threadIdx.x, lane = tid & 31, wid = tid >> 5;
    int wr = wid / WC, wc = wid % WC;
    int m0 = blockIdx.y * BM, n0 = blockIdx.x * BN;

    const float* Ag = A + (long)m0 * lda;
    const float* Bg = B + (long)n0 * ldb;

    float acc[MT][NT][4];
    #pragma unroll
    for (int i = 0; i < MT; i++)
        #pragma unroll
        for (int j = 0; j < NT; j++)
            #pragma unroll
            for (int e = 0; e < 4; e++) acc[i][j][e] = 0.f;

    int arow[NA4], acol[NA4], brow[NB4], bcol[NB4];
    #pragma unroll
    for (int i = 0; i < NA4; i++) { int f = tid + i * 256; arow[i] = f >> 3; acol[i] = (f & 7) * 4; }
    #pragma unroll
    for (int i = 0; i < NB4; i++) { int f = tid + i * 256; brow[i] = f >> 3; bcol[i] = (f & 7) * 4; }

    {
        #pragma unroll
        for (int i = 0; i < NA4; i++) {
            float4 v = *reinterpret_cast<const float4*>(Ag + (long)arow[i] * lda + acol[i]);
            uint32_t* d = As + arow[i] * PAD + acol[i];
            d[0] = f2tf(v.x); d[1] = f2tf(v.y); d[2] = f2tf(v.z); d[3] = f2tf(v.w);
        }
        #pragma unroll
        for (int i = 0; i < NB4; i++) {
            float4 v = *reinterpret_cast<const float4*>(Bg + (long)brow[i] * ldb + bcol[i]);
            uint32_t* d = Bs + brow[i] * PAD + bcol[i];
            d[0] = f2tf(v.x); d[1] = f2tf(v.y); d[2] = f2tf(v.z); d[3] = f2tf(v.w);
        }
    }
    __syncthreads();

    int nCh = K >> 5;
    for (int c = 0; c < nCh; ++c) {
        int buf = c & 1;
        float4 pa[NA4], pb[NB4];
        if (c + 1 < nCh) {
            const float* An = Ag + (c + 1) * BK;
            const float* Bn = Bg + (c + 1) * BK;
            #pragma unroll
            for (int i = 0; i < NA4; i++)
                pa[i] = *reinterpret_cast<const float4*>(An + (long)arow[i] * lda + acol[i]);
            #pragma unroll
            for (int i = 0; i < NB4; i++)
                pb[i] = *reinterpret_cast<const float4*>(Bn + (long)brow[i] * ldb + bcol[i]);
        }

        const uint32_t* Ab = As + buf * ASZ + (wr * WM) * PAD;
        const uint32_t* Bb = Bs + buf * BSZ + (wc * WN) * PAD;
        int qr = lane >> 2, qc = lane & 3;

        #pragma unroll
        for (int ks = 0; ks < 4; ++ks) {
            int kk = ks * 8;
            uint32_t af[MT][4], bf[NT][2];
            #pragma unroll
            for (int mt = 0; mt < MT; mt++) {
                const uint32_t* p = Ab + (mt * 16 + qr) * PAD + kk + qc;
                af[mt][0] = p[0];
                af[mt][1] = p[8 * PAD];
                af[mt][2] = p[4];
                af[mt][3] = p[8 * PAD + 4];
            }
            #pragma unroll
            for (int nt = 0; nt < NT; nt++) {
                const uint32_t* p = Bb + (nt * 8 + qr) * PAD + kk + qc;
                bf[nt][0] = p[0];
                bf[nt][1] = p[4];
            }
            #pragma unroll
            for (int mt = 0; mt < MT; mt++)
                #pragma unroll
                for (int nt = 0; nt < NT; nt++)
                    mma_tf32(acc[mt][nt], af[mt], bf[nt]);
        }

        if (c + 1 < nCh) {
            uint32_t* Ad = As + (buf ^ 1) * ASZ;
            uint32_t* Bd = Bs + (buf ^ 1) * BSZ;
            #pragma unroll
            for (int i = 0; i < NA4; i++) {
                uint32_t* d = Ad + arow[i] * PAD + acol[i];
                d[0] = f2tf(pa[i].x); d[1] = f2tf(pa[i].y);
                d[2] = f2tf(pa[i].z); d[3] = f2tf(pa[i].w);
            }
            #pragma unroll
            for (int i = 0; i < NB4; i++) {
                uint32_t* d = Bd + brow[i] * PAD + bcol[i];
                d[0] = f2tf(pb[i].x); d[1] = f2tf(pb[i].y);
                d[2] = f2tf(pb[i].z); d[3] = f2tf(pb[i].w);
            }
        }
        __syncthreads();
    }

    int qr = lane >> 2, qc = lane & 3;
    #pragma unroll
    for (int mt = 0; mt < MT; mt++) {
        #pragma unroll
        for (int half = 0; half < 2; half++) {
            int row = m0 + wr * WM + mt * 16 + qr + half * 8;
            float* Crow = C + (long)row * ldc;
            const float* Rrow = (EPI == 1) ? (resid + (long)row * ldr) : nullptr;
            #pragma unroll
            for (int nt = 0; nt < NT; nt++) {
                int col = n0 + wc * WN + nt * 8 + 2 * qc;
                float v0 = acc[mt][nt][half * 2 + 0];
                float v1 = acc[mt][nt][half * 2 + 1];
                if (EPI == 1) {
                    v0 += bias[col]     + Rrow[col];
                    v1 += bias[col + 1] + Rrow[col + 1];
                } else if (EPI == 2) {
                    v0 += bias[col];
                    v1 += bias[col + 1];
                    v0 = 0.5f * v0 * (1.0f + erff(v0 * 0.70710678118654752f));
                    v1 = 0.5f * v1 * (1.0f + erff(v1 * 0.70710678118654752f));
                }
                *reinterpret_cast<float2*>(&Crow[col]) = make_float2(v0, v1);
            }
        }
    }
}

// ---------------- launcher ----------------
extern "C" void kernel_launch(void* const* d_in, const int* in_sizes, int n_in,
                              void* d_out, int out_size)
{
    const float* x    = (const float*)d_in[0];
    const float* ln1g = (const float*)d_in[1];
    const float* ln1b = (const float*)d_in[2];
    const float* wq   = (const float*)d_in[3];
    const float* wk   = (const float*)d_in[4];
    const float* wv   = (const float*)d_in[5];
    const float* wo   = (const float*)d_in[6];
    const float* bo   = (const float*)d_in[7];
    const float* ln2g = (const float*)d_in[8];
    const float* ln2b = (const float*)d_in[9];
    const float* w1   = (const float*)d_in[10];
    const float* b1   = (const float*)d_in[11];
    const float* w2   = (const float*)d_in[12];
    const float* b2   = (const float*)d_in[13];
    float* out = (float*)d_out;

    float *xn, *qb, *kb, *vb, *attn, *x1, *hm, *w1t, *w2t;
    cudaGetSymbolAddress((void**)&xn,   g_xn);
    cudaGetSymbolAddress((void**)&qb,   g_q);
    cudaGetSymbolAddress((void**)&kb,   g_k);
    cudaGetSymbolAddress((void**)&vb,   g_v);
    cudaGetSymbolAddress((void**)&attn, g_attn);
    cudaGetSymbolAddress((void**)&x1,   g_x1);
    cudaGetSymbolAddress((void**)&hm,   g_h);
    cudaGetSymbolAddress((void**)&w1t,  g_w1t);
    cudaGetSymbolAddress((void**)&w2t,  g_w2t);

    const int SMLG = 2 * (128 + 256) * PAD * 4;                 // 110592
    const int SMFL = (2 * 128 * FPK + 64 * FPV) * 4;            // 103680
    cudaFuncSetAttribute((const void*)gemm_mma<128,256,2,4,0>, cudaFuncAttributeMaxDynamicSharedMemorySize, SMLG);
    cudaFuncSetAttribute((const void*)gemm_mma<128,256,2,4,1>, cudaFuncAttributeMaxDynamicSharedMemorySize, SMLG);
    cudaFuncSetAttribute((const void*)gemm_mma<128,256,2,4,2>, cudaFuncAttributeMaxDynamicSharedMemorySize, SMLG);
    cudaFuncSetAttribute((const void*)flash_k, cudaFuncAttributeMaxDynamicSharedMemorySize, SMFL);

    // weight transposes
    transpose_k<<<dim3(MLPH / 32, HIDDEN / 32), 256>>>(w1, MLPH, w1t, HIDDEN);
    transpose_k<<<dim3(HIDDEN / 32, MLPH / 32), 256>>>(w2, HIDDEN, w2t, MLPH);

    // 1. LN1
    ln_k<<<MTOK, 256>>>(x, ln1g, ln1b, xn);

    // 2. QKV (M=16384, N=768, K=768) NT
    dim3 gQKV(HIDDEN / 256, MTOK / 128);
    gemm_mma<128,256,2,4,0><<<gQKV, 256, SMLG>>>(xn, HIDDEN, wq, HIDDEN, qb, HIDDEN, HIDDEN, nullptr, nullptr, 0);
    gemm_mma<128,256,2,4,0><<<gQKV, 256, SMLG>>>(xn, HIDDEN, wk, HIDDEN, kb, HIDDEN, HIDDEN, nullptr, nullptr, 0);
    gemm_mma<128,256,2,4,0><<<gQKV, 256, SMLG>>>(xn, HIDDEN, wv, HIDDEN, vb, HIDDEN, HIDDEN, nullptr, nullptr, 0);

    // 3. fused attention -> attn
    flash_k<<<dim3(SEQ / 128, BATCH * HEADS), 256, SMFL>>>(qb, kb, vb, attn);

    // 4. x1 = attn @ wo^T + bo + x
    gemm_mma<128,256,2,4,1><<<gQKV, 256, SMLG>>>(attn, HIDDEN, wo, HIDDEN, x1, HIDDEN, HIDDEN, bo, x, HIDDEN);

    // 5. LN2
    ln_k<<<MTOK, 256>>>(x1, ln2g, ln2b, xn);

    // 6. h = gelu(xn @ w1 + b1)
    gemm_mma<128,256,2,4,2><<<dim3(MLPH / 256, MTOK / 128), 256, SMLG>>>(
        xn, HIDDEN, w1t, HIDDEN, hm, MLPH, HIDDEN, b1, nullptr, 0);

    // 7. out = h @ w2 + b2 + x1
    gemm_mma<128,256,2,4,1><<<gQKV, 256, SMLG>>>(hm, MLPH, w2t, MLPH, out, HIDDEN, MLPH, b2, x1, HIDDEN);
}

// round 6
// speedup vs baseline: 3.4177x; 1.0621x over previous
#include <cuda_runtime.h>
#include <math.h>
#include <stdint.h>

// ---------------- problem constants ----------------
#define HIDDEN   768
#define MLPH     3072
#define HEADS    12
#define HEAD_DIM 64
#define BATCH    16
#define SEQ      1024
#define MTOK     (BATCH * SEQ)

// ---------------- scratch (device globals; no allocation) ----------------
__device__ float g_xn  [(size_t)MTOK * HIDDEN];
__device__ float g_q   [(size_t)MTOK * HIDDEN];
__device__ float g_k   [(size_t)MTOK * HIDDEN];
__device__ float g_v   [(size_t)MTOK * HIDDEN];
__device__ float g_attn[(size_t)MTOK * HIDDEN];
__device__ float g_x1  [(size_t)MTOK * HIDDEN];
__device__ float g_h   [(size_t)MTOK * MLPH];
__device__ float g_w1t [(size_t)MLPH * HIDDEN];
__device__ float g_w2t [(size_t)HIDDEN * MLPH];

// ---------------- helpers ----------------
__device__ __forceinline__ uint32_t f2tf(float f) {
    uint32_t r; asm("cvt.rna.tf32.f32 %0, %1;" : "=r"(r) : "f"(f)); return r;
}
__device__ __forceinline__ uint32_t smem_u32(const void* p) {
    uint32_t a;
    asm("{ .reg .u64 t; cvta.to.shared.u64 t, %1; cvt.u32.u64 %0, t; }" : "=r"(a) : "l"(p));
    return a;
}
__device__ __forceinline__ void ldsm4(uint32_t* r, uint32_t addr) {
    asm volatile("ldmatrix.sync.aligned.m8n8.x4.shared.b16 {%0,%1,%2,%3}, [%4];"
                 : "=r"(r[0]), "=r"(r[1]), "=r"(r[2]), "=r"(r[3]) : "r"(addr));
}
__device__ __forceinline__ void mma_tf32(float* d, const uint32_t* a, const uint32_t* b) {
    asm volatile("mma.sync.aligned.m16n8k8.row.col.f32.tf32.tf32.f32 "
                 "{%0,%1,%2,%3}, {%4,%5,%6,%7}, {%8,%9}, {%0,%1,%2,%3};"
                 : "+f"(d[0]), "+f"(d[1]), "+f"(d[2]), "+f"(d[3])
                 : "r"(a[0]), "r"(a[1]), "r"(a[2]), "r"(a[3]), "r"(b[0]), "r"(b[1]));
}
__device__ __forceinline__ float warp_sum(float v) {
    #pragma unroll
    for (int o = 16; o; o >>= 1) v += __shfl_xor_sync(0xffffffffu, v, o);
    return v;
}
__device__ __forceinline__ float warp_max(float v) {
    #pragma unroll
    for (int o = 16; o; o >>= 1) v = fmaxf(v, __shfl_xor_sync(0xffffffffu, v, o));
    return v;
}

// ---------------- LayerNorm ----------------
__global__ __launch_bounds__(256)
void ln_k(const float* __restrict__ x, const float* __restrict__ g,
          const float* __restrict__ b, float* __restrict__ out)
{
    long row = blockIdx.x;
    const float* xr = x + row * (long)HIDDEN;
    int tid = threadIdx.x;
    float v0 = xr[tid], v1 = xr[tid + 256], v2 = xr[tid + 512];
    float s  = v0 + v1 + v2;
    float s2 = v0 * v0 + v1 * v1 + v2 * v2;
    __shared__ float sh[18];
    s = warp_sum(s); s2 = warp_sum(s2);
    int w = tid >> 5, l = tid & 31;
    if (!l) { sh[w] = s; sh[w + 8] = s2; }
    __syncthreads();
    if (tid == 0) {
        float ts = 0.f, ts2 = 0.f;
        #pragma unroll
        for (int i = 0; i < 8; i++) { ts += sh[i]; ts2 += sh[i + 8]; }
        float mu  = ts * (1.0f / HIDDEN);
        float var = ts2 * (1.0f / HIDDEN) - mu * mu;
        sh[16] = mu; sh[17] = rsqrtf(var + 1e-5f);
    }
    __syncthreads();
    float mu = sh[16], inv = sh[17];
    float* o = out + row * (long)HIDDEN;
    o[tid]       = (v0 - mu) * inv * g[tid]       + b[tid];
    o[tid + 256] = (v1 - mu) * inv * g[tid + 256] + b[tid + 256];
    o[tid + 512] = (v2 - mu) * inv * g[tid + 512] + b[tid + 512];
}

// ---------------- transpose (weights) ----------------
__global__ __launch_bounds__(256)
void transpose_k(const float* __restrict__ in, int ldi,
                 float* __restrict__ out, int ldo)
{
    __shared__ float t[32][33];
    int c0 = blockIdx.x * 32, r0 = blockIdx.y * 32;
    int tx = threadIdx.x & 31, ty = threadIdx.x >> 5;
    #pragma unroll
    for (int i = ty; i < 32; i += 8)
        t[i][tx] = in[(long)(r0 + i) * ldi + c0 + tx];
    __syncthreads();
    #pragma unroll
    for (int i = ty; i < 32; i += 8)
        out[(long)(c0 + i) * ldo + r0 + tx] = t[tx][i];
}

// ---------------- flash attention ----------------
#define FPK 68    // Ks/Qs row stride (words)
#define FPV 133   // Vs row stride (words)

__global__ __launch_bounds__(256)
void flash_k(const float* __restrict__ Q, const float* __restrict__ Kg,
             const float* __restrict__ Vg, float* __restrict__ Og)
{
    extern __shared__ uint32_t sm[];
    uint32_t* Qs = sm;                     // [128][FPK]
    uint32_t* Ks = sm + 128 * FPK;         // [128][FPK]
    uint32_t* Vs = sm + 2 * 128 * FPK;     // [64][FPV]  (V transposed: [dim][key])

    int tid = threadIdx.x, lane = tid & 31, wid = tid >> 5;
    int qr = lane >> 2, qc = lane & 3;
    int z = blockIdx.y;
    int b = z / HEADS, h = z - b * HEADS;
    int q0 = blockIdx.x * 128;
    long tokbase = (long)b * SEQ + q0;

    const float* Qp = Q  + tokbase * HIDDEN + h * HEAD_DIM;
    const float* Kp = Kg + (long)b * SEQ * HIDDEN + h * HEAD_DIM;
    const float* Vp = Vg + (long)b * SEQ * HIDDEN + h * HEAD_DIM;

    // ldmatrix lane offsets (A-pattern for Q, B-pattern for K)
    uint32_t qAddr = smem_u32(Qs) +
        (((wid * 16 + ((lane >> 3) & 1) * 8 + (lane & 7)) * FPK + (lane >> 4) * 4) << 2);
    uint32_t kAddr = smem_u32(Ks) +
        ((((lane >> 4) * 8 + (lane & 7)) * FPK + ((lane >> 3) & 1) * 4) << 2);

    // stage Q tile (128x64) as tf32
    #pragma unroll
    for (int i = 0; i < 8; i++) {
        int idx = tid + i * 256; int t = idx >> 4, c = idx & 15;
        float4 v = *reinterpret_cast<const float4*>(Qp + (long)t * HIDDEN + c * 4);
        uint32_t* d = Qs + t * FPK + c * 4;
        d[0] = f2tf(v.x); d[1] = f2tf(v.y); d[2] = f2tf(v.z); d[3] = f2tf(v.w);
    }
    __syncthreads();

    // persistent Q fragments
    uint32_t qf[8][4];
    #pragma unroll
    for (int ks = 0; ks < 8; ks++)
        ldsm4(qf[ks], qAddr + ks * 32);

    float oa[8][4];
    #pragma unroll
    for (int i = 0; i < 8; i++)
        #pragma unroll
        for (int e = 0; e < 4; e++) oa[i][e] = 0.f;
    float mA = -1e30f, mB = -1e30f, lA = 0.f, lB = 0.f;
    const float scale = 0.125f;

    for (int ch = 0; ch < SEQ / 128; ch++) {
        __syncthreads();
        const float* Kc = Kp + (long)ch * 128 * HIDDEN;
        const float* Vc = Vp + (long)ch * 128 * HIDDEN;
        #pragma unroll
        for (int i = 0; i < 8; i++) {
            int idx = tid + i * 256; int t = idx >> 4, c = idx & 15;
            float4 v = *reinterpret_cast<const float4*>(Kc + (long)t * HIDDEN + c * 4);
            uint32_t* d = Ks + t * FPK + c * 4;
            d[0] = f2tf(v.x); d[1] = f2tf(v.y); d[2] = f2tf(v.z); d[3] = f2tf(v.w);
        }
        #pragma unroll
        for (int i = 0; i < 8; i++) {
            int idx = tid + i * 256; int t = idx >> 4, c = idx & 15;
            float4 v = *reinterpret_cast<const float4*>(Vc + (long)t * HIDDEN + c * 4);
            Vs[(4 * c + 0) * FPV + t] = f2tf(v.x);
            Vs[(4 * c + 1) * FPV + t] = f2tf(v.y);
            Vs[(4 * c + 2) * FPV + t] = f2tf(v.z);
            Vs[(4 * c + 3) * FPV + t] = f2tf(v.w);
        }
        __syncthreads();

        // S = Q @ K^T : warp tile 16 x 128 (K frags via ldmatrix, 2 nt per LDSM)
        float sa[16][4];
        #pragma unroll
        for (int i = 0; i < 16; i++)
            #pragma unroll
            for (int e = 0; e < 4; e++) sa[i][e] = 0.f;
        #pragma unroll
        for (int ks = 0; ks < 8; ks++) {
            #pragma unroll
            for (int ntp = 0; ntp < 8; ntp++) {
                uint32_t kf[4];
                ldsm4(kf, kAddr + ((ntp * 16 * FPK + ks * 8) << 2));
                mma_tf32(sa[2 * ntp + 0], qf[ks], kf);
                mma_tf32(sa[2 * ntp + 1], qf[ks], kf + 2);
            }
        }

        // online softmax
        float rmA = -1e30f, rmB = -1e30f;
        #pragma unroll
        for (int nt = 0; nt < 16; nt++) {
            rmA = fmaxf(rmA, fmaxf(sa[nt][0], sa[nt][1]));
            rmB = fmaxf(rmB, fmaxf(sa[nt][2], sa[nt][3]));
        }
        rmA = fmaxf(rmA, __shfl_xor_sync(0xffffffffu, rmA, 1));
        rmA = fmaxf(rmA, __shfl_xor_sync(0xffffffffu, rmA, 2));
        rmB = fmaxf(rmB, __shfl_xor_sync(0xffffffffu, rmB, 1));
        rmB = fmaxf(rmB, __shfl_xor_sync(0xffffffffu, rmB, 2));
        float mAn = fmaxf(mA, rmA), mBn = fmaxf(mB, rmB);
        float aA = __expf((mA - mAn) * scale), aB = __expf((mB - mBn) * scale);
        float sA = 0.f, sB = 0.f;
        #pragma unroll
        for (int nt = 0; nt < 16; nt++) {
            sa[nt][0] = __expf((sa[nt][0] - mAn) * scale);
            sa[nt][1] = __expf((sa[nt][1] - mAn) * scale);
            sa[nt][2] = __expf((sa[nt][2] - mBn) * scale);
            sa[nt][3] = __expf((sa[nt][3] - mBn) * scale);
            sA += sa[nt][0] + sa[nt][1];
            sB += sa[nt][2] + sa[nt][3];
        }
        sA += __shfl_xor_sync(0xffffffffu, sA, 1);
        sA += __shfl_xor_sync(0xffffffffu, sA, 2);
        sB += __shfl_xor_sync(0xffffffffu, sB, 1);
        sB += __shfl_xor_sync(0xffffffffu, sB, 2);
        lA = aA * lA + sA;  lB = aB * lB + sB;
        mA = mAn;  mB = mBn;
        #pragma unroll
        for (int nt = 0; nt < 8; nt++) {
            oa[nt][0] *= aA; oa[nt][1] *= aA;
            oa[nt][2] *= aB; oa[nt][3] *= aB;
        }

        // O += P @ V
        int s0 = (lane & ~3) | (qc >> 1);
        int s1 = s0 + 2;
        bool hi = qc & 1;
        #pragma unroll
        for (int kk = 0; kk < 16; kk++) {
            uint32_t p0 = f2tf(sa[kk][0]), p1 = f2tf(sa[kk][1]);
            uint32_t p2 = f2tf(sa[kk][2]), p3 = f2tf(sa[kk][3]);
            uint32_t u0 = __shfl_sync(0xffffffffu, p0, s0);
            uint32_t u1 = __shfl_sync(0xffffffffu, p1, s0);
            uint32_t v0 = __shfl_sync(0xffffffffu, p2, s0);
            uint32_t v1 = __shfl_sync(0xffffffffu, p3, s0);
            uint32_t w0 = __shfl_sync(0xffffffffu, p0, s1);
            uint32_t w1 = __shfl_sync(0xffffffffu, p1, s1);
            uint32_t x0 = __shfl_sync(0xffffffffu, p2, s1);
            uint32_t x1 = __shfl_sync(0xffffffffu, p3, s1);
            uint32_t af[4];
            af[0] = hi ? u1 : u0;  af[1] = hi ? v1 : v0;
            af[2] = hi ? w1 : w0;  af[3] = hi ? x1 : x0;
            #pragma unroll
            for (int nt = 0; nt < 8; nt++) {
                const uint32_t* p = Vs + (nt * 8 + qr) * FPV + kk * 8 + qc;
                uint32_t bf[2] = { p[0], p[4] };
                mma_tf32(oa[nt], af, bf);
            }
        }
    }

    // epilogue
    float rA = 1.f / lA, rB = 1.f / lB;
    long rowA = tokbase + wid * 16 + qr;
    float* OA = Og + rowA * HIDDEN + h * HEAD_DIM;
    float* OB = OA + 8 * HIDDEN;
    #pragma unroll
    for (int nt = 0; nt < 8; nt++) {
        int col = nt * 8 + 2 * qc;
        *reinterpret_cast<float2*>(OA + col) = make_float2(oa[nt][0] * rA, oa[nt][1] * rA);
        *reinterpret_cast<float2*>(OB + col) = make_float2(oa[nt][2] * rB, oa[nt][3] * rB);
    }
}

// ---------------- TF32 mma.sync NT GEMM (ldmatrix fragments) ----------------
#define PAD 36

template<int BM, int BN, int WR, int WC, int EPI>
__global__ __launch_bounds__(256)
void gemm_mma(const float* __restrict__ A, int lda,
              const float* __restrict__ B, int ldb,
              float* __restrict__ C, int ldc,
              int K,
              const float* __restrict__ bias,
              const float* __restrict__ resid, int ldr)
{
    constexpr int BK = 32;
    constexpr int WM = BM / WR, WN = BN / WC;
    constexpr int MT = WM / 16, NT = WN / 8;
    constexpr int NA4 = BM / 32;
    constexpr int NB4 = BN / 32;
    constexpr int ASZ = BM * PAD;
    constexpr int BSZ = BN * PAD;

    extern __shared__ uint32_t sm[];
    uint32_t* As = sm;
    uint32_t* Bs = sm + 2 * ASZ;

    int tid = threadIdx.x, lane = tid & 31, wid = tid >> 5;
    int wr = wid / WC, wc = wid % WC;
    int m0 = blockIdx.y * BM, n0 = blockIdx.x * BN;

    const float* Ag = A + (long)m0 * lda;
    const float* Bg = B + (long)n0 * ldb;

    // ldmatrix per-thread byte offsets
    uint32_t aLM = smem_u32(As) +
        (((wr * WM + ((lane >> 3) & 1) * 8 + (lane & 7)) * PAD + (lane >> 4) * 4) << 2);
    uint32_t bLM = smem_u32(Bs) +
        (((wc * WN + (lane >> 4) * 8 + (lane & 7)) * PAD + ((lane >> 3) & 1) * 4) << 2);

    float acc[MT][NT][4];
    #pragma unroll
    for (int i = 0; i < MT; i++)
        #pragma unroll
        for (int j = 0; j < NT; j++)
            #pragma unroll
            for (int e = 0; e < 4; e++) acc[i][j][e] = 0.f;

    int arow[NA4], acol[NA4], brow[NB4], bcol[NB4];
    #pragma unroll
    for (int i = 0; i < NA4; i++) { int f = tid + i * 256; arow[i] = f >> 3; acol[i] = (f & 7) * 4; }
    #pragma unroll
    for (int i = 0; i < NB4; i++) { int f = tid + i * 256; brow[i] = f >> 3; bcol[i] = (f & 7) * 4; }

    {
        #pragma unroll
        for (int i = 0; i < NA4; i++) {
            float4 v = *reinterpret_cast<const float4*>(Ag + (long)arow[i] * lda + acol[i]);
            uint32_t* d = As + arow[i] * PAD + acol[i];
            d[0] = f2tf(v.x); d[1] = f2tf(v.y); d[2] = f2tf(v.z); d[3] = f2tf(v.w);
        }
        #pragma unroll
        for (int i = 0; i < NB4; i++) {
            float4 v = *reinterpret_cast<const float4*>(Bg + (long)brow[i] * ldb + bcol[i]);
            uint32_t* d = Bs + brow[i] * PAD + bcol[i];
            d[0] = f2tf(v.x); d[1] = f2tf(v.y); d[2] = f2tf(v.z); d[3] = f2tf(v.w);
        }
    }
    __syncthreads();

    int nCh = K >> 5;
    for (int c = 0; c < nCh; ++c) {
        int buf = c & 1;
        float4 pa[NA4], pb[NB4];
        if (c + 1 < nCh) {
            const float* An = Ag + (c + 1) * BK;
            const float* Bn = Bg + (c + 1) * BK;
            #pragma unroll
            for (int i = 0; i < NA4; i++)
                pa[i] = *reinterpret_cast<const float4*>(An + (long)arow[i] * lda + acol[i]);
            #pragma unroll
            for (int i = 0; i < NB4; i++)
                pb[i] = *reinterpret_cast<const float4*>(Bn + (long)brow[i] * ldb + bcol[i]);
        }

        uint32_t aB = aLM + buf * (ASZ << 2);
        uint32_t bB = bLM + buf * (BSZ << 2);

        #pragma unroll
        for (int ks = 0; ks < 4; ++ks) {
            int kk = ks * 8;
            uint32_t af[MT][4], bf[NT][2];
            #pragma unroll
            for (int mt = 0; mt < MT; mt++)
                ldsm4(af[mt], aB + ((mt * 16 * PAD + kk) << 2));
            #pragma unroll
            for (int ntp = 0; ntp < NT / 2; ntp++)
                ldsm4(&bf[2 * ntp][0], bB + ((ntp * 16 * PAD + kk) << 2));
            #pragma unroll
            for (int mt = 0; mt < MT; mt++)
                #pragma unroll
                for (int nt = 0; nt < NT; nt++)
                    mma_tf32(acc[mt][nt], af[mt], bf[nt]);
        }

        if (c + 1 < nCh) {
            uint32_t* Ad = As + (buf ^ 1) * ASZ;
            uint32_t* Bd = Bs + (buf ^ 1) * BSZ;
            #pragma unroll
            for (int i = 0; i < NA4; i++) {
                uint32_t* d = Ad + arow[i] * PAD + acol[i];
                d[0] = f2tf(pa[i].x); d[1] = f2tf(pa[i].y);
                d[2] = f2tf(pa[i].z); d[3] = f2tf(pa[i].w);
            }
            #pragma unroll
            for (int i = 0; i < NB4; i++) {
                uint32_t* d = Bd + brow[i] * PAD + bcol[i];
                d[0] = f2tf(pb[i].x); d[1] = f2tf(pb[i].y);
                d[2] = f2tf(pb[i].z); d[3] = f2tf(pb[i].w);
            }
        }
        __syncthreads();
    }

    int qr = lane >> 2, qc = lane & 3;
    #pragma unroll
    for (int mt = 0; mt < MT; mt++) {
        #pragma unroll
        for (int half = 0; half < 2; half++) {
            int row = m0 + wr * WM + mt * 16 + qr + half * 8;
            float* Crow = C + (long)row * ldc;
            const float* Rrow = (EPI == 1) ? (resid + (long)row * ldr) : nullptr;
            #pragma unroll
            for (int nt = 0; nt < NT; nt++) {
                int col = n0 + wc * WN + nt * 8 + 2 * qc;
                float v0 = acc[mt][nt][half * 2 + 0];
                float v1 = acc[mt][nt][half * 2 + 1];
                if (EPI == 1) {
                    v0 += bias[col]     + Rrow[col];
                    v1 += bias[col + 1] + Rrow[col + 1];
                } else if (EPI == 2) {
                    v0 += bias[col];
                    v1 += bias[col + 1];
                    v0 = 0.5f * v0 * (1.0f + erff(v0 * 0.70710678118654752f));
                    v1 = 0.5f * v1 * (1.0f + erff(v1 * 0.70710678118654752f));
                }
                *reinterpret_cast<float2*>(&Crow[col]) = make_float2(v0, v1);
            }
        }
    }
}

// ---------------- launcher ----------------
extern "C" void kernel_launch(void* const* d_in, const int* in_sizes, int n_in,
                              void* d_out, int out_size)
{
    const float* x    = (const float*)d_in[0];
    const float* ln1g = (const float*)d_in[1];
    const float* ln1b = (const float*)d_in[2];
    const float* wq   = (const float*)d_in[3];
    const float* wk   = (const float*)d_in[4];
    const float* wv   = (const float*)d_in[5];
    const float* wo   = (const float*)d_in[6];
    const float* bo   = (const float*)d_in[7];
    const float* ln2g = (const float*)d_in[8];
    const float* ln2b = (const float*)d_in[9];
    const float* w1   = (const float*)d_in[10];
    const float* b1   = (const float*)d_in[11];
    const float* w2   = (const float*)d_in[12];
    const float* b2   = (const float*)d_in[13];
    float* out = (float*)d_out;

    float *xn, *qb, *kb, *vb, *attn, *x1, *hm, *w1t, *w2t;
    cudaGetSymbolAddress((void**)&xn,   g_xn);
    cudaGetSymbolAddress((void**)&qb,   g_q);
    cudaGetSymbolAddress((void**)&kb,   g_k);
    cudaGetSymbolAddress((void**)&vb,   g_v);
    cudaGetSymbolAddress((void**)&attn, g_attn);
    cudaGetSymbolAddress((void**)&x1,   g_x1);
    cudaGetSymbolAddress((void**)&hm,   g_h);
    cudaGetSymbolAddress((void**)&w1t,  g_w1t);
    cudaGetSymbolAddress((void**)&w2t,  g_w2t);

    const int SMLG = 2 * (128 + 256) * PAD * 4;                 // 110592
    const int SMFL = (2 * 128 * FPK + 64 * FPV) * 4;            // 103680
    cudaFuncSetAttribute((const void*)gemm_mma<128,256,2,4,0>, cudaFuncAttributeMaxDynamicSharedMemorySize, SMLG);
    cudaFuncSetAttribute((const void*)gemm_mma<128,256,2,4,1>, cudaFuncAttributeMaxDynamicSharedMemorySize, SMLG);
    cudaFuncSetAttribute((const void*)gemm_mma<128,256,2,4,2>, cudaFuncAttributeMaxDynamicSharedMemorySize, SMLG);
    cudaFuncSetAttribute((const void*)flash_k, cudaFuncAttributeMaxDynamicSharedMemorySize, SMFL);

    // weight transposes
    transpose_k<<<dim3(MLPH / 32, HIDDEN / 32), 256>>>(w1, MLPH, w1t, HIDDEN);
    transpose_k<<<dim3(HIDDEN / 32, MLPH / 32), 256>>>(w2, HIDDEN, w2t, MLPH);

    // 1. LN1
    ln_k<<<MTOK, 256>>>(x, ln1g, ln1b, xn);

    // 2. QKV (M=16384, N=768, K=768) NT
    dim3 gQKV(HIDDEN / 256, MTOK / 128);
    gemm_mma<128,256,2,4,0><<<gQKV, 256, SMLG>>>(xn, HIDDEN, wq, HIDDEN, qb, HIDDEN, HIDDEN, nullptr, nullptr, 0);
    gemm_mma<128,256,2,4,0><<<gQKV, 256, SMLG>>>(xn, HIDDEN, wk, HIDDEN, kb, HIDDEN, HIDDEN, nullptr, nullptr, 0);
    gemm_mma<128,256,2,4,0><<<gQKV, 256, SMLG>>>(xn, HIDDEN, wv, HIDDEN, vb, HIDDEN, HIDDEN, nullptr, nullptr, 0);

    // 3. fused attention -> attn
    flash_k<<<dim3(SEQ / 128, BATCH * HEADS), 256, SMFL>>>(qb, kb, vb, attn);

    // 4. x1 = attn @ wo^T + bo + x
    gemm_mma<128,256,2,4,1><<<gQKV, 256, SMLG>>>(attn, HIDDEN, wo, HIDDEN, x1, HIDDEN, HIDDEN, bo, x, HIDDEN);

    // 5. LN2
    ln_k<<<MTOK, 256>>>(x1, ln2g, ln2b, xn);

    // 6. h = gelu(xn @ w1 + b1)
    gemm_mma<128,256,2,4,2><<<dim3(MLPH / 256, MTOK / 128), 256, SMLG>>>(
        xn, HIDDEN, w1t, HIDDEN, hm, MLPH, HIDDEN, b1, nullptr, 0);

    // 7. out = h @ w2 + b2 + x1
    gemm_mma<128,256,2,4,1><<<gQKV, 256, SMLG>>>(hm, MLPH, w2t, MLPH, out, HIDDEN, MLPH, b2, x1, HIDDEN);
}

// round 7
// speedup vs baseline: 3.7953x; 1.1105x over previous
#include <cuda_runtime.h>
#include <math.h>
#include <stdint.h>

// ---------------- problem constants ----------------
#define HIDDEN   768
#define MLPH     3072
#define HEADS    12
#define HEAD_DIM 64
#define BATCH    16
#define SEQ      1024
#define MTOK     (BATCH * SEQ)

// ---------------- scratch (device globals; no allocation) ----------------
__device__ float g_xn  [(size_t)MTOK * HIDDEN];
__device__ float g_q   [(size_t)MTOK * HIDDEN];
__device__ float g_k   [(size_t)MTOK * HIDDEN];
__device__ float g_v   [(size_t)MTOK * HIDDEN];
__device__ float g_attn[(size_t)MTOK * HIDDEN];
__device__ float g_x1  [(size_t)MTOK * HIDDEN];
__device__ float g_h   [(size_t)MTOK * MLPH];
__device__ float g_w1t [(size_t)MLPH * HIDDEN];
__device__ float g_w2t [(size_t)HIDDEN * MLPH];
__device__ float g_wq  [(size_t)HIDDEN * HIDDEN];
__device__ float g_wk  [(size_t)HIDDEN * HIDDEN];
__device__ float g_wv  [(size_t)HIDDEN * HIDDEN];
__device__ float g_wo  [(size_t)HIDDEN * HIDDEN];

// ---------------- helpers ----------------
__device__ __forceinline__ uint32_t f2tf(float f) {
    uint32_t r; asm("cvt.rna.tf32.f32 %0, %1;" : "=r"(r) : "f"(f)); return r;
}
__device__ __forceinline__ float tfr(float f) { return __uint_as_float(f2tf(f)); }
__device__ __forceinline__ uint32_t smem_u32(const void* p) {
    uint32_t a;
    asm("{ .reg .u64 t; cvta.to.shared.u64 t, %1; cvt.u32.u64 %0, t; }" : "=r"(a) : "l"(p));
    return a;
}
__device__ __forceinline__ void ldsm4(uint32_t* r, uint32_t addr) {
    asm volatile("ldmatrix.sync.aligned.m8n8.x4.shared.b16 {%0,%1,%2,%3}, [%4];"
                 : "=r"(r[0]), "=r"(r[1]), "=r"(r[2]), "=r"(r[3]) : "r"(addr));
}
__device__ __forceinline__ void cp16(uint32_t saddr, const void* g) {
    asm volatile("cp.async.ca.shared.global [%0], [%1], 16;" :: "r"(saddr), "l"(g) : "memory");
}
__device__ __forceinline__ void cp_commit() {
    asm volatile("cp.async.commit_group;" ::: "memory");
}
__device__ __forceinline__ void cp_wait0() {
    asm volatile("cp.async.wait_group 0;" ::: "memory");
}
__device__ __forceinline__ void mma_tf32(float* d, const uint32_t* a, const uint32_t* b) {
    asm volatile("mma.sync.aligned.m16n8k8.row.col.f32.tf32.tf32.f32 "
                 "{%0,%1,%2,%3}, {%4,%5,%6,%7}, {%8,%9}, {%0,%1,%2,%3};"
                 : "+f"(d[0]), "+f"(d[1]), "+f"(d[2]), "+f"(d[3])
                 : "r"(a[0]), "r"(a[1]), "r"(a[2]), "r"(a[3]), "r"(b[0]), "r"(b[1]));
}
__device__ __forceinline__ float warp_sum(float v) {
    #pragma unroll
    for (int o = 16; o; o >>= 1) v += __shfl_xor_sync(0xffffffffu, v, o);
    return v;
}
__device__ __forceinline__ float warp_max(float v) {
    #pragma unroll
    for (int o = 16; o; o >>= 1) v = fmaxf(v, __shfl_xor_sync(0xffffffffu, v, o));
    return v;
}

// ---------------- elementwise tf32 round-copy ----------------
__global__ __launch_bounds__(256)
void roundcpy_k(const float* __restrict__ in, float* __restrict__ out, int n4)
{
    int i = blockIdx.x * 256 + threadIdx.x;
    if (i < n4) {
        float4 v = reinterpret_cast<const float4*>(in)[i];
        v.x = tfr(v.x); v.y = tfr(v.y); v.z = tfr(v.z); v.w = tfr(v.w);
        reinterpret_cast<float4*>(out)[i] = v;
    }
}

// ---------------- LayerNorm (output rounded to tf32) ----------------
__global__ __launch_bounds__(256)
void ln_k(const float* __restrict__ x, const float* __restrict__ g,
          const float* __restrict__ b, float* __restrict__ out)
{
    long row = blockIdx.x;
    const float* xr = x + row * (long)HIDDEN;
    int tid = threadIdx.x;
    float v0 = xr[tid], v1 = xr[tid + 256], v2 = xr[tid + 512];
    float s  = v0 + v1 + v2;
    float s2 = v0 * v0 + v1 * v1 + v2 * v2;
    __shared__ float sh[18];
    s = warp_sum(s); s2 = warp_sum(s2);
    int w = tid >> 5, l = tid & 31;
    if (!l) { sh[w] = s; sh[w + 8] = s2; }
    __syncthreads();
    if (tid == 0) {
        float ts = 0.f, ts2 = 0.f;
        #pragma unroll
        for (int i = 0; i < 8; i++) { ts += sh[i]; ts2 += sh[i + 8]; }
        float mu  = ts * (1.0f / HIDDEN);
        float var = ts2 * (1.0f / HIDDEN) - mu * mu;
        sh[16] = mu; sh[17] = rsqrtf(var + 1e-5f);
    }
    __syncthreads();
    float mu = sh[16], inv = sh[17];
    float* o = out + row * (long)HIDDEN;
    o[tid]       = tfr((v0 - mu) * inv * g[tid]       + b[tid]);
    o[tid + 256] = tfr((v1 - mu) * inv * g[tid + 256] + b[tid + 256]);
    o[tid + 512] = tfr((v2 - mu) * inv * g[tid + 512] + b[tid + 512]);
}

// ---------------- transpose + tf32 round (weights) ----------------
__global__ __launch_bounds__(256)
void transpose_k(const float* __restrict__ in, int ldi,
                 float* __restrict__ out, int ldo)
{
    __shared__ float t[32][33];
    int c0 = blockIdx.x * 32, r0 = blockIdx.y * 32;
    int tx = threadIdx.x & 31, ty = threadIdx.x >> 5;
    #pragma unroll
    for (int i = ty; i < 32; i += 8)
        t[i][tx] = in[(long)(r0 + i) * ldi + c0 + tx];
    __syncthreads();
    #pragma unroll
    for (int i = ty; i < 32; i += 8)
        out[(long)(c0 + i) * ldo + r0 + tx] = tfr(t[tx][i]);
}

// ---------------- flash attention (inputs pre-rounded tf32) ----------------
#define FPK 68
#define FPV 133

__global__ __launch_bounds__(256)
void flash_k(const float* __restrict__ Q, const float* __restrict__ Kg,
             const float* __restrict__ Vg, float* __restrict__ Og)
{
    extern __shared__ uint32_t sm[];
    uint32_t* Qs = sm;
    uint32_t* Ks = sm + 128 * FPK;
    uint32_t* Vs = sm + 2 * 128 * FPK;

    int tid = threadIdx.x, lane = tid & 31, wid = tid >> 5;
    int qr = lane >> 2, qc = lane & 3;
    int z = blockIdx.y;
    int b = z / HEADS, h = z - b * HEADS;
    int q0 = blockIdx.x * 128;
    long tokbase = (long)b * SEQ + q0;

    const float* Qp = Q  + tokbase * HIDDEN + h * HEAD_DIM;
    const float* Kp = Kg + (long)b * SEQ * HIDDEN + h * HEAD_DIM;
    const float* Vp = Vg + (long)b * SEQ * HIDDEN + h * HEAD_DIM;

    uint32_t qAddr = smem_u32(Qs) +
        (((wid * 16 + ((lane >> 3) & 1) * 8 + (lane & 7)) * FPK + (lane >> 4) * 4) << 2);
    uint32_t kAddr = smem_u32(Ks) +
        ((((lane >> 4) * 8 + (lane & 7)) * FPK + ((lane >> 3) & 1) * 4) << 2);

    #pragma unroll
    for (int i = 0; i < 8; i++) {
        int idx = tid + i * 256; int t = idx >> 4, c = idx & 15;
        float4 v = *reinterpret_cast<const float4*>(Qp + (long)t * HIDDEN + c * 4);
        uint32_t* d = Qs + t * FPK + c * 4;
        d[0] = __float_as_uint(v.x); d[1] = __float_as_uint(v.y);
        d[2] = __float_as_uint(v.z); d[3] = __float_as_uint(v.w);
    }
    __syncthreads();

    uint32_t qf[8][4];
    #pragma unroll
    for (int ks = 0; ks < 8; ks++)
        ldsm4(qf[ks], qAddr + ks * 32);

    float oa[8][4];
    #pragma unroll
    for (int i = 0; i < 8; i++)
        #pragma unroll
        for (int e = 0; e < 4; e++) oa[i][e] = 0.f;
    float mA = -1e30f, mB = -1e30f, lA = 0.f, lB = 0.f;
    const float scale = 0.125f;

    for (int ch = 0; ch < SEQ / 128; ch++) {
        __syncthreads();
        const float* Kc = Kp + (long)ch * 128 * HIDDEN;
        const float* Vc = Vp + (long)ch * 128 * HIDDEN;
        #pragma unroll
        for (int i = 0; i < 8; i++) {
            int idx = tid + i * 256; int t = idx >> 4, c = idx & 15;
            float4 v = *reinterpret_cast<const float4*>(Kc + (long)t * HIDDEN + c * 4);
            uint32_t* d = Ks + t * FPK + c * 4;
            d[0] = __float_as_uint(v.x); d[1] = __float_as_uint(v.y);
            d[2] = __float_as_uint(v.z); d[3] = __float_as_uint(v.w);
        }
        #pragma unroll
        for (int i = 0; i < 8; i++) {
            int idx = tid + i * 256; int t = idx >> 4, c = idx & 15;
            float4 v = *reinterpret_cast<const float4*>(Vc + (long)t * HIDDEN + c * 4);
            Vs[(4 * c + 0) * FPV + t] = __float_as_uint(v.x);
            Vs[(4 * c + 1) * FPV + t] = __float_as_uint(v.y);
            Vs[(4 * c + 2) * FPV + t] = __float_as_uint(v.z);
            Vs[(4 * c + 3) * FPV + t] = __float_as_uint(v.w);
        }
        __syncthreads();

        float sa[16][4];
        #pragma unroll
        for (int i = 0; i < 16; i++)
            #pragma unroll
            for (int e = 0; e < 4; e++) sa[i][e] = 0.f;
        #pragma unroll
        for (int ks = 0; ks < 8; ks++) {
            #pragma unroll
            for (int ntp = 0; ntp < 8; ntp++) {
                uint32_t kf[4];
                ldsm4(kf, kAddr + ((ntp * 16 * FPK + ks * 8) << 2));
                mma_tf32(sa[2 * ntp + 0], qf[ks], kf);
                mma_tf32(sa[2 * ntp + 1], qf[ks], kf + 2);
            }
        }

        float rmA = -1e30f, rmB = -1e30f;
        #pragma unroll
        for (int nt = 0; nt < 16; nt++) {
            rmA = fmaxf(rmA, fmaxf(sa[nt][0], sa[nt][1]));
            rmB = fmaxf(rmB, fmaxf(sa[nt][2], sa[nt][3]));
        }
        rmA = fmaxf(rmA, __shfl_xor_sync(0xffffffffu, rmA, 1));
        rmA = fmaxf(rmA, __shfl_xor_sync(0xffffffffu, rmA, 2));
        rmB = fmaxf(rmB, __shfl_xor_sync(0xffffffffu, rmB, 1));
        rmB = fmaxf(rmB, __shfl_xor_sync(0xffffffffu, rmB, 2));
        float mAn = fmaxf(mA, rmA), mBn = fmaxf(mB, rmB);
        float aA = __expf((mA - mAn) * scale), aB = __expf((mB - mBn) * scale);
        float sA = 0.f, sB = 0.f;
        #pragma unroll
        for (int nt = 0; nt < 16; nt++) {
            sa[nt][0] = __expf((sa[nt][0] - mAn) * scale);
            sa[nt][1] = __expf((sa[nt][1] - mAn) * scale);
            sa[nt][2] = __expf((sa[nt][2] - mBn) * scale);
            sa[nt][3] = __expf((sa[nt][3] - mBn) * scale);
            sA += sa[nt][0] + sa[nt][1];
            sB += sa[nt][2] + sa[nt][3];
        }
        sA += __shfl_xor_sync(0xffffffffu, sA, 1);
        sA += __shfl_xor_sync(0xffffffffu, sA, 2);
        sB += __shfl_xor_sync(0xffffffffu, sB, 1);
        sB += __shfl_xor_sync(0xffffffffu, sB, 2);
        lA = aA * lA + sA;  lB = aB * lB + sB;
        mA = mAn;  mB = mBn;
        #pragma unroll
        for (int nt = 0; nt < 8; nt++) {
            oa[nt][0] *= aA; oa[nt][1] *= aA;
            oa[nt][2] *= aB; oa[nt][3] *= aB;
        }

        int s0 = (lane & ~3) | (qc >> 1);
        int s1 = s0 + 2;
        bool hi = qc & 1;
        #pragma unroll
        for (int kk = 0; kk < 16; kk++) {
            uint32_t p0 = f2tf(sa[kk][0]), p1 = f2tf(sa[kk][1]);
            uint32_t p2 = f2tf(sa[kk][2]), p3 = f2tf(sa[kk][3]);
            uint32_t u0 = __shfl_sync(0xffffffffu, p0, s0);
            uint32_t u1 = __shfl_sync(0xffffffffu, p1, s0);
            uint32_t v0 = __shfl_sync(0xffffffffu, p2, s0);
            uint32_t v1 = __shfl_sync(0xffffffffu, p3, s0);
            uint32_t w0 = __shfl_sync(0xffffffffu, p0, s1);
            uint32_t w1 = __shfl_sync(0xffffffffu, p1, s1);
            uint32_t x0 = __shfl_sync(0xffffffffu, p2, s1);
            uint32_t x1 = __shfl_sync(0xffffffffu, p3, s1);
            uint32_t af[4];
            af[0] = hi ? u1 : u0;  af[1] = hi ? v1 : v0;
            af[2] = hi ? w1 : w0;  af[3] = hi ? x1 : x0;
            #pragma unroll
            for (int nt = 0; nt < 8; nt++) {
                const uint32_t* p = Vs + (nt * 8 + qr) * FPV + kk * 8 + qc;
                uint32_t bf[2] = { p[0], p[4] };
                mma_tf32(oa[nt], af, bf);
            }
        }
    }

    // epilogue: round attn to tf32 (it feeds the WO GEMM as A operand)
    float rA = 1.f / lA, rB = 1.f / lB;
    long rowA = tokbase + wid * 16 + qr;
    float* OA = Og + rowA * HIDDEN + h * HEAD_DIM;
    float* OB = OA + 8 * HIDDEN;
    #pragma unroll
    for (int nt = 0; nt < 8; nt++) {
        int col = nt * 8 + 2 * qc;
        *reinterpret_cast<float2*>(OA + col) = make_float2(tfr(oa[nt][0] * rA), tfr(oa[nt][1] * rA));
        *reinterpret_cast<float2*>(OB + col) = make_float2(tfr(oa[nt][2] * rB), tfr(oa[nt][3] * rB));
    }
}

// ---------------- cp.async TF32 GEMM, 128x128, 2 CTAs/SM ----------------
// A, B already tf32-rounded. C = A[M,K] @ B[N,K]^T.
// EPI: 0 store rounded, 1 +bias+resid (full fp32), 2 +bias,GELU, rounded.
template<int EPI>
__global__ __launch_bounds__(256, 2)
void gemm_ca(const float* __restrict__ A, int lda,
             const float* __restrict__ B, int ldb,
             float* __restrict__ C, int ldc, int K,
             const float* __restrict__ bias,
             const float* __restrict__ resid, int ldr)
{
    constexpr int MT = 4, NT = 4;
    constexpr int BUF = 8192;         // words per buffer (A 4096 + B 4096)
    extern __shared__ uint32_t sm[];
    uint32_t sbase = smem_u32(sm);

    int tid = threadIdx.x, lane = tid & 31, wid = tid >> 5;
    int wr = wid >> 2, wc = wid & 3;
    int m0 = blockIdx.y * 128, n0 = blockIdx.x * 128;

    const float* Ag = A + (long)m0 * lda;
    const float* Bg = B + (long)n0 * ldb;

    // staging: thread handles 4 units in A and 4 in B per chunk
    int srow = tid >> 3, sc = tid & 7;

    // ldmatrix row bases
    int rA = wr * 64 + ((lane >> 3) & 1) * 8 + (lane & 7);
    int rB = wc * 32 + (lane >> 4) * 8 + (lane & 7);
    int a7 = rA & 7, b7 = rB & 7;
    int hiA = lane >> 4, hiB = (lane >> 3) & 1;

    float acc[MT][NT][4];
    #pragma unroll
    for (int i = 0; i < MT; i++)
        #pragma unroll
        for (int j = 0; j < NT; j++)
            #pragma unroll
            for (int e = 0; e < 4; e++) acc[i][j][e] = 0.f;

    int nCh = K >> 5;

    // prologue: stage chunk 0 into buffer 0
    #pragma unroll
    for (int i = 0; i < 4; i++) {
        int row = srow + i * 32;
        int u = sc ^ (row & 7);
        cp16(sbase + ((row * 32 + u * 4) << 2), Ag + (long)row * lda + sc * 4);
        cp16(sbase + ((4096 + row * 32 + u * 4) << 2), Bg + (long)row * ldb + sc * 4);
    }
    cp_commit();

    for (int c = 0; c < nCh; ++c) {
        int buf = c & 1;
        cp_wait0();
        __syncthreads();
        if (c + 1 < nCh) {
            const float* An = Ag + (c + 1) * 32;
            const float* Bn = Bg + (c + 1) * 32;
            uint32_t dst = sbase + (((buf ^ 1) * BUF) << 2);
            #pragma unroll
            for (int i = 0; i < 4; i++) {
                int row = srow + i * 32;
                int u = sc ^ (row & 7);
                cp16(dst + ((row * 32 + u * 4) << 2), An + (long)row * lda + sc * 4);
                cp16(dst + ((4096 + row * 32 + u * 4) << 2), Bn + (long)row * ldb + sc * 4);
            }
            cp_commit();
        }

        uint32_t aB = sbase + ((buf * BUF) << 2);
        uint32_t bB = aB + (4096 << 2);

        #pragma unroll
        for (int ks = 0; ks < 4; ++ks) {
            uint32_t af[MT][4], bf[NT][2];
            int uA = ((ks * 2 + hiA) ^ a7) * 4;
            int uB = ((ks * 2 + hiB) ^ b7) * 4;
            #pragma unroll
            for (int mt = 0; mt < MT; mt++)
                ldsm4(af[mt], aB + (((rA + mt * 16) * 32 + uA) << 2));
            #pragma unroll
            for (int ntp = 0; ntp < 2; ntp++)
                ldsm4(&bf[2 * ntp][0], bB + (((rB + ntp * 16) * 32 + uB) << 2));
            #pragma unroll
            for (int mt = 0; mt < MT; mt++)
                #pragma unroll
                for (int nt = 0; nt < NT; nt++)
                    mma_tf32(acc[mt][nt], af[mt], bf[nt]);
        }
        __syncthreads();
    }

    int qr = lane >> 2, qc = lane & 3;
    #pragma unroll
    for (int mt = 0; mt < MT; mt++) {
        #pragma unroll
        for (int half = 0; half < 2; half++) {
            int row = m0 + wr * 64 + mt * 16 + qr + half * 8;
            float* Crow = C + (long)row * ldc;
            const float* Rrow = (EPI == 1) ? (resid + (long)row * ldr) : nullptr;
            #pragma unroll
            for (int nt = 0; nt < NT; nt++) {
                int col = n0 + wc * 32 + nt * 8 + 2 * qc;
                float v0 = acc[mt][nt][half * 2 + 0];
                float v1 = acc[mt][nt][half * 2 + 1];
                if (EPI == 1) {
                    v0 += bias[col]     + Rrow[col];
                    v1 += bias[col + 1] + Rrow[col + 1];
                } else if (EPI == 2) {
                    v0 += bias[col];
                    v1 += bias[col + 1];
                    v0 = tfr(0.5f * v0 * (1.0f + erff(v0 * 0.70710678118654752f)));
                    v1 = tfr(0.5f * v1 * (1.0f + erff(v1 * 0.70710678118654752f)));
                } else {
                    v0 = tfr(v0); v1 = tfr(v1);
                }
                *reinterpret_cast<float2*>(&Crow[col]) = make_float2(v0, v1);
            }
        }
    }
}

// ---------------- launcher ----------------
extern "C" void kernel_launch(void* const* d_in, const int* in_sizes, int n_in,
                              void* d_out, int out_size)
{
    const float* x    = (const float*)d_in[0];
    const float* ln1g = (const float*)d_in[1];
    const float* ln1b = (const float*)d_in[2];
    const float* wq   = (const float*)d_in[3];
    const float* wk   = (const float*)d_in[4];
    const float* wv   = (const float*)d_in[5];
    const float* wo   = (const float*)d_in[6];
    const float* bo   = (const float*)d_in[7];
    const float* ln2g = (const float*)d_in[8];
    const float* ln2b = (const float*)d_in[9];
    const float* w1   = (const float*)d_in[10];
    const float* b1   = (const float*)d_in[11];
    const float* w2   = (const float*)d_in[12];
    const float* b2   = (const float*)d_in[13];
    float* out = (float*)d_out;

    float *xn, *qb, *kb, *vb, *attn, *x1, *hm, *w1t, *w2t, *rwq, *rwk, *rwv, *rwo;
    cudaGetSymbolAddress((void**)&xn,   g_xn);
    cudaGetSymbolAddress((void**)&qb,   g_q);
    cudaGetSymbolAddress((void**)&kb,   g_k);
    cudaGetSymbolAddress((void**)&vb,   g_v);
    cudaGetSymbolAddress((void**)&attn, g_attn);
    cudaGetSymbolAddress((void**)&x1,   g_x1);
    cudaGetSymbolAddress((void**)&hm,   g_h);
    cudaGetSymbolAddress((void**)&w1t,  g_w1t);
    cudaGetSymbolAddress((void**)&w2t,  g_w2t);
    cudaGetSymbolAddress((void**)&rwq,  g_wq);
    cudaGetSymbolAddress((void**)&rwk,  g_wk);
    cudaGetSymbolAddress((void**)&rwv,  g_wv);
    cudaGetSymbolAddress((void**)&rwo,  g_wo);

    const int SMGE = 2 * 8192 * 4;                    // 65536
    const int SMFL = (2 * 128 * FPK + 64 * FPV) * 4;  // 103680
    cudaFuncSetAttribute((const void*)gemm_ca<0>, cudaFuncAttributeMaxDynamicSharedMemorySize, SMGE);
    cudaFuncSetAttribute((const void*)gemm_ca<1>, cudaFuncAttributeMaxDynamicSharedMemorySize, SMGE);
    cudaFuncSetAttribute((const void*)gemm_ca<2>, cudaFuncAttributeMaxDynamicSharedMemorySize, SMGE);
    cudaFuncSetAttribute((const void*)flash_k, cudaFuncAttributeMaxDynamicSharedMemorySize, SMFL);

    // weight prep: round QKV/O weights; transpose+round MLP weights
    int nw = HIDDEN * HIDDEN / 4;
    roundcpy_k<<<(nw + 255) / 256, 256>>>(wq, rwq, nw);
    roundcpy_k<<<(nw + 255) / 256, 256>>>(wk, rwk, nw);
    roundcpy_k<<<(nw + 255) / 256, 256>>>(wv, rwv, nw);
    roundcpy_k<<<(nw + 255) / 256, 256>>>(wo, rwo, nw);
    transpose_k<<<dim3(MLPH / 32, HIDDEN / 32), 256>>>(w1, MLPH, w1t, HIDDEN);
    transpose_k<<<dim3(HIDDEN / 32, MLPH / 32), 256>>>(w2, HIDDEN, w2t, MLPH);

    // 1. LN1 (rounded output)
    ln_k<<<MTOK, 256>>>(x, ln1g, ln1b, xn);

    // 2. QKV (M=16384, N=768, K=768)
    dim3 gQKV(HIDDEN / 128, MTOK / 128);
    gemm_ca<0><<<gQKV, 256, SMGE>>>(xn, HIDDEN, rwq, HIDDEN, qb, HIDDEN, HIDDEN, nullptr, nullptr, 0);
    gemm_ca<0><<<gQKV, 256, SMGE>>>(xn, HIDDEN, rwk, HIDDEN, kb, HIDDEN, HIDDEN, nullptr, nullptr, 0);
    gemm_ca<0><<<gQKV, 256, SMGE>>>(xn, HIDDEN, rwv, HIDDEN, vb, HIDDEN, HIDDEN, nullptr, nullptr, 0);

    // 3. fused attention (rounded output)
    flash_k<<<dim3(SEQ / 128, BATCH * HEADS), 256, SMFL>>>(qb, kb, vb, attn);

    // 4. x1 = attn @ wo^T + bo + x (full fp32)
    gemm_ca<1><<<gQKV, 256, SMGE>>>(attn, HIDDEN, rwo, HIDDEN, x1, HIDDEN, HIDDEN, bo, x, HIDDEN);

    // 5. LN2 (rounded output)
    ln_k<<<MTOK, 256>>>(x1, ln2g, ln2b, xn);

    // 6. h = gelu(xn @ w1 + b1) (rounded output)
    gemm_ca<2><<<dim3(MLPH / 128, MTOK / 128), 256, SMGE>>>(
        xn, HIDDEN, w1t, HIDDEN, hm, MLPH, HIDDEN, b1, nullptr, 0);

    // 7. out = h @ w2 + b2 + x1 (full fp32)
    gemm_ca<1><<<gQKV, 256, SMGE>>>(hm, MLPH, w2t, MLPH, out, HIDDEN, MLPH, b2, x1, HIDDEN);
}